// round 5
// baseline (speedup 1.0000x reference)
#include <cuda_runtime.h>
#include <math.h>
#include <stdint.h>

// Problem constants
constexpr int BB  = 4;
constexpr int SS  = 2048;
constexpr int DD  = 1024;
constexpr int HH  = 16;
constexpr int DK  = 64;
constexpr int DFF = 4096;
constexpr int MM  = BB * SS;           // 8192 rows

// -------- scratch (device globals: no allocation allowed) --------
__device__ float g_xn  [(size_t)MM * DD];   // layernorm output (reused for ln1 and ln2)
__device__ float g_q   [(size_t)MM * DD];
__device__ float g_k   [(size_t)MM * DD];
__device__ float g_v   [(size_t)MM * DD];
__device__ float g_attn[(size_t)MM * DD];
__device__ float g_ffn [(size_t)MM * DFF];

// ============================================================================
// LayerNorm: per-row, D=1024, ddof=1 (unbiased std), denom = std + eps
// ============================================================================
__global__ __launch_bounds__(256) void ln_kernel(
    const float* __restrict__ x, const float* __restrict__ w,
    const float* __restrict__ b, float* __restrict__ out)
{
    const int row = blockIdx.x;
    const int tid = threadIdx.x;
    const float4* xr = (const float4*)(x + (size_t)row * DD);
    float4 v = xr[tid];

    float s  = v.x + v.y + v.z + v.w;
    float s2 = v.x*v.x + v.y*v.y + v.z*v.z + v.w*v.w;
    #pragma unroll
    for (int off = 16; off; off >>= 1) {
        s  += __shfl_xor_sync(0xffffffffu, s,  off);
        s2 += __shfl_xor_sync(0xffffffffu, s2, off);
    }
    __shared__ float rs[8], rs2[8];
    if ((tid & 31) == 0) { rs[tid >> 5] = s; rs2[tid >> 5] = s2; }
    __syncthreads();
    float ts = 0.f, ts2 = 0.f;
    #pragma unroll
    for (int i = 0; i < 8; i++) { ts += rs[i]; ts2 += rs2[i]; }

    const float mean = ts * (1.0f / (float)DD);
    float var = (ts2 - (float)DD * mean * mean) * (1.0f / (float)(DD - 1));
    var = fmaxf(var, 0.0f);
    const float inv = 1.0f / (sqrtf(var) + 1e-6f);

    float4 wv = ((const float4*)w)[tid];
    float4 bv = ((const float4*)b)[tid];
    float4 o;
    o.x = wv.x * (v.x - mean) * inv + bv.x;
    o.y = wv.y * (v.y - mean) * inv + bv.y;
    o.z = wv.z * (v.z - mean) * inv + bv.z;
    o.w = wv.w * (v.w - mean) * inv + bv.w;
    ((float4*)(out + (size_t)row * DD))[tid] = o;
}

// ============================================================================
// SGEMM: C[M,N] = epi(A[M,K] @ W[K,N] + bias).  128x128 tile, BK=8, 8x8/thread.
// EPI: 0 = bias only, 1 = bias+relu, 2 = bias + residual
// ============================================================================
template<int EPI>
__global__ __launch_bounds__(256, 2) void sgemm_kernel(
    const float* __restrict__ A, const float* __restrict__ W,
    const float* __restrict__ bias, const float* __restrict__ resid,
    float* __restrict__ C, int N, int K)
{
    __shared__ float As[8][128];
    __shared__ float Bs[8][128];

    const int tid  = threadIdx.x;
    const int row0 = blockIdx.y * 128;
    const int col0 = blockIdx.x * 128;

    const int arow = tid >> 1;
    const int acol = (tid & 1) << 2;
    const int brow = tid >> 5;
    const int bcol = (tid & 31) << 2;

    const float* Ap = A + (size_t)(row0 + arow) * K + acol;
    const float* Bp = W + (size_t)brow * N + col0 + bcol;

    const int tx = tid & 15, ty = tid >> 4;
    const int cr = ty << 3, cc = tx << 3;

    float acc[8][8];
    #pragma unroll
    for (int i = 0; i < 8; i++)
        #pragma unroll
        for (int j = 0; j < 8; j++) acc[i][j] = 0.0f;

    for (int k0 = 0; k0 < K; k0 += 8) {
        float4 av = *(const float4*)Ap;
        float4 bv = *(const float4*)Bp;
        As[acol + 0][arow] = av.x;
        As[acol + 1][arow] = av.y;
        As[acol + 2][arow] = av.z;
        As[acol + 3][arow] = av.w;
        *(float4*)&Bs[brow][bcol] = bv;
        __syncthreads();

        #pragma unroll
        for (int kk = 0; kk < 8; kk++) {
            float af[8], bf[8];
            *(float4*)(af)     = *(const float4*)&As[kk][cr];
            *(float4*)(af + 4) = *(const float4*)&As[kk][cr + 4];
            *(float4*)(bf)     = *(const float4*)&Bs[kk][cc];
            *(float4*)(bf + 4) = *(const float4*)&Bs[kk][cc + 4];
            #pragma unroll
            for (int i = 0; i < 8; i++)
                #pragma unroll
                for (int j = 0; j < 8; j++)
                    acc[i][j] = fmaf(af[i], bf[j], acc[i][j]);
        }
        __syncthreads();
        Ap += 8;
        Bp += (size_t)8 * N;
    }

    float bvals[8];
    #pragma unroll
    for (int j = 0; j < 8; j++) bvals[j] = bias[col0 + cc + j];

    #pragma unroll
    for (int i = 0; i < 8; i++) {
        const size_t ro = (size_t)(row0 + cr + i) * N + col0 + cc;
        float t[8];
        #pragma unroll
        for (int j = 0; j < 8; j++) t[j] = acc[i][j] + bvals[j];
        if (EPI == 1) {
            #pragma unroll
            for (int j = 0; j < 8; j++) t[j] = fmaxf(t[j], 0.0f);
        }
        if (EPI == 2) {
            float4 r0v = *(const float4*)(resid + ro);
            float4 r1v = *(const float4*)(resid + ro + 4);
            t[0] += r0v.x; t[1] += r0v.y; t[2] += r0v.z; t[3] += r0v.w;
            t[4] += r1v.x; t[5] += r1v.y; t[6] += r1v.z; t[7] += r1v.w;
        }
        float4 o0 = make_float4(t[0], t[1], t[2], t[3]);
        float4 o1 = make_float4(t[4], t[5], t[6], t[7]);
        *(float4*)(C + ro)     = o0;
        *(float4*)(C + ro + 4) = o1;
    }
}

// ============================================================================
// Flash attention (fp32, online softmax). One block = 64 queries of one (b,h).
// Key/value tiles of 64. smem pitch 68 for conflict-free float4 fragments.
// ============================================================================
constexpr int FPITCH = 68;
constexpr int FLASH_SMEM = 4 * 64 * FPITCH * 4 + 64 * 4;  // Qt,Kt,Vs,Pt + mask

__global__ __launch_bounds__(256) void flash_kernel(
    const float* __restrict__ q, const float* __restrict__ k,
    const float* __restrict__ v, const int* __restrict__ mask,
    float* __restrict__ out)
{
    extern __shared__ float sm[];
    float* Qt = sm;                     // [d][r]  64 x 68
    float* Kt = sm + 64 * FPITCH;       // [d][c]
    float* Vs = sm + 2 * 64 * FPITCH;   // [c][d]
    float* Pt = sm + 3 * 64 * FPITCH;   // [c][r]
    int*  msk = (int*)(sm + 4 * 64 * FPITCH);

    const int tid = threadIdx.x;
    const int b = blockIdx.z, h = blockIdx.y;
    const int q0 = blockIdx.x * 64;
    const int tx = tid & 15, ty = tid >> 4;
    const int r0 = ty << 2, c0 = tx << 2;

    // load Q tile transposed: Qt[d][r]
    {
        const float* qb = q + ((size_t)(b * SS + q0)) * DD + h * DK;
        #pragma unroll
        for (int it = 0; it < 16; it++) {
            int idx = it * 256 + tid;
            int r = idx >> 6, d = idx & 63;
            Qt[d * FPITCH + r] = qb[(size_t)r * DD + d];
        }
    }

    float o[4][4];
    #pragma unroll
    for (int i = 0; i < 4; i++)
        #pragma unroll
        for (int j = 0; j < 4; j++) o[i][j] = 0.0f;
    float mrow[4], lrow[4];
    #pragma unroll
    for (int i = 0; i < 4; i++) { mrow[i] = -INFINITY; lrow[i] = 0.0f; }

    for (int kt = 0; kt < SS; kt += 64) {
        // load K (transposed) and V tiles
        const float* kb = k + ((size_t)(b * SS + kt)) * DD + h * DK;
        const float* vb = v + ((size_t)(b * SS + kt)) * DD + h * DK;
        #pragma unroll
        for (int it = 0; it < 16; it++) {
            int idx = it * 256 + tid;
            int r = idx >> 6, d = idx & 63;
            Kt[d * FPITCH + r] = kb[(size_t)r * DD + d];
            Vs[r * FPITCH + d] = vb[(size_t)r * DD + d];
        }
        if (tid < 64) msk[tid] = mask[(size_t)b * SS + kt + tid];
        __syncthreads();

        // S = Q K^T (scaled) for this thread's 4x4 sub-tile
        float s[4][4];
        #pragma unroll
        for (int i = 0; i < 4; i++)
            #pragma unroll
            for (int j = 0; j < 4; j++) s[i][j] = 0.0f;
        #pragma unroll 8
        for (int d = 0; d < 64; d++) {
            float4 a  = *(const float4*)&Qt[d * FPITCH + r0];
            float4 bb = *(const float4*)&Kt[d * FPITCH + c0];
            const float af[4] = {a.x, a.y, a.z, a.w};
            const float bf[4] = {bb.x, bb.y, bb.z, bb.w};
            #pragma unroll
            for (int i = 0; i < 4; i++)
                #pragma unroll
                for (int j = 0; j < 4; j++)
                    s[i][j] = fmaf(af[i], bf[j], s[i][j]);
        }

        // online softmax per row (row spread over 16 tx lanes; width-16 shuffles)
        #pragma unroll
        for (int i = 0; i < 4; i++) {
            float sj[4];
            #pragma unroll
            for (int j = 0; j < 4; j++) {
                float t = s[i][j] * 0.125f;          // 1/sqrt(64)
                sj[j] = (msk[c0 + j] == 0) ? -INFINITY : t;
            }
            float mx = fmaxf(fmaxf(sj[0], sj[1]), fmaxf(sj[2], sj[3]));
            #pragma unroll
            for (int off = 8; off; off >>= 1)
                mx = fmaxf(mx, __shfl_xor_sync(0xffffffffu, mx, off, 16));
            float mnew  = fmaxf(mrow[i], mx);
            float alpha = expf(mrow[i] - mnew);
            float p[4], rs = 0.0f;
            #pragma unroll
            for (int j = 0; j < 4; j++) { p[j] = expf(sj[j] - mnew); rs += p[j]; }
            #pragma unroll
            for (int off = 8; off; off >>= 1)
                rs += __shfl_xor_sync(0xffffffffu, rs, off, 16);
            lrow[i] = lrow[i] * alpha + rs;
            mrow[i] = mnew;
            #pragma unroll
            for (int d = 0; d < 4; d++) o[i][d] *= alpha;
            #pragma unroll
            for (int j = 0; j < 4; j++) Pt[(c0 + j) * FPITCH + r0 + i] = p[j];
        }
        __syncthreads();

        // O += P @ V
        #pragma unroll 8
        for (int j = 0; j < 64; j++) {
            float4 a  = *(const float4*)&Pt[j * FPITCH + r0];
            float4 vv = *(const float4*)&Vs[j * FPITCH + c0];
            const float af[4] = {a.x, a.y, a.z, a.w};
            const float vf[4] = {vv.x, vv.y, vv.z, vv.w};
            #pragma unroll
            for (int i = 0; i < 4; i++)
                #pragma unroll
                for (int d = 0; d < 4; d++)
                    o[i][d] = fmaf(af[i], vf[d], o[i][d]);
        }
        __syncthreads();   // before next tile overwrites Kt/Vs/Pt
    }

    // finalize and store: out[b, q0+r, h*64 + d]
    float* ob = out + ((size_t)(b * SS + q0 + r0)) * DD + h * DK + c0;
    #pragma unroll
    for (int i = 0; i < 4; i++) {
        float inv = 1.0f / lrow[i];
        float4 w = make_float4(o[i][0] * inv, o[i][1] * inv,
                               o[i][2] * inv, o[i][3] * inv);
        *(float4*)(ob + (size_t)i * DD) = w;
    }
}

// ============================================================================
// kernel_launch: 9 graph-capturable launches, no allocation, default stream
// ============================================================================
extern "C" void kernel_launch(void* const* d_in, const int* in_sizes, int n_in,
                              void* d_out, int out_size)
{
    const float* x    = (const float*)d_in[0];
    const int*   mask = (const int*)  d_in[1];
    const float* wq   = (const float*)d_in[2];
    const float* bq   = (const float*)d_in[3];
    const float* wk   = (const float*)d_in[4];
    const float* bk   = (const float*)d_in[5];
    const float* wv   = (const float*)d_in[6];
    const float* bv   = (const float*)d_in[7];
    const float* wo   = (const float*)d_in[8];
    const float* bo   = (const float*)d_in[9];
    const float* w1   = (const float*)d_in[10];
    const float* b1   = (const float*)d_in[11];
    const float* w2   = (const float*)d_in[12];
    const float* b2   = (const float*)d_in[13];
    const float* ln1w = (const float*)d_in[14];
    const float* ln1b = (const float*)d_in[15];
    const float* ln2w = (const float*)d_in[16];
    const float* ln2b = (const float*)d_in[17];
    float* out = (float*)d_out;

    float *xn, *qq, *kk, *vv, *attn, *ffn;
    cudaGetSymbolAddress((void**)&xn,   g_xn);
    cudaGetSymbolAddress((void**)&qq,   g_q);
    cudaGetSymbolAddress((void**)&kk,   g_k);
    cudaGetSymbolAddress((void**)&vv,   g_v);
    cudaGetSymbolAddress((void**)&attn, g_attn);
    cudaGetSymbolAddress((void**)&ffn,  g_ffn);

    cudaFuncSetAttribute(flash_kernel,
                         cudaFuncAttributeMaxDynamicSharedMemorySize, FLASH_SMEM);

    // 1. ln1
    ln_kernel<<<MM, 256>>>(x, ln1w, ln1b, xn);

    // 2-4. Q, K, V projections (M=8192, N=1024, K=1024)
    dim3 g1(DD / 128, MM / 128);
    sgemm_kernel<0><<<g1, 256>>>(xn, wq, bq, nullptr, qq, DD, DD);
    sgemm_kernel<0><<<g1, 256>>>(xn, wk, bk, nullptr, kk, DD, DD);
    sgemm_kernel<0><<<g1, 256>>>(xn, wv, bv, nullptr, vv, DD, DD);

    // 5. attention
    dim3 gf(SS / 64, HH, BB);
    flash_kernel<<<gf, 256, FLASH_SMEM>>>(qq, kk, vv, mask, attn);

    // 6. O projection + residual -> h1 in d_out
    sgemm_kernel<2><<<g1, 256>>>(attn, wo, bo, x, out, DD, DD);

    // 7. ln2
    ln_kernel<<<MM, 256>>>(out, ln2w, ln2b, xn);

    // 8. FFN up + relu (N=4096)
    dim3 g2(DFF / 128, MM / 128);
    sgemm_kernel<1><<<g2, 256>>>(xn, w1, b1, nullptr, ffn, DFF, DD);

    // 9. FFN down + residual (K=4096), in-place on d_out
    sgemm_kernel<2><<<g1, 256>>>(ffn, w2, b2, out, out, DD, DFF);
}

// round 7
// speedup vs baseline: 1.7027x; 1.7027x over previous
#include <cuda_runtime.h>
#include <cuda_bf16.h>
#include <math.h>
#include <stdint.h>

// Problem constants
constexpr int BB  = 4;
constexpr int SS  = 2048;
constexpr int DD  = 1024;
constexpr int HH  = 16;
constexpr int DK  = 64;
constexpr int DFF = 4096;
constexpr int MM  = BB * SS;           // 8192 rows

// ---------------- scratch (device globals; allocation is forbidden) --------
__device__ __nv_bfloat16 g_xnh [(size_t)MM * DD];
__device__ __nv_bfloat16 g_xnl [(size_t)MM * DD];
__device__ float         g_q   [(size_t)MM * DD];
__device__ float         g_k   [(size_t)MM * DD];
__device__ float         g_v   [(size_t)MM * DD];
__device__ __nv_bfloat16 g_ath [(size_t)MM * DD];
__device__ __nv_bfloat16 g_atl [(size_t)MM * DD];
__device__ __nv_bfloat16 g_ffh [(size_t)MM * DFF];
__device__ __nv_bfloat16 g_ffl [(size_t)MM * DFF];
// transposed + split weights: [N,K] K-major bf16
__device__ __nv_bfloat16 g_wqh[DD*DD],  g_wql[DD*DD];
__device__ __nv_bfloat16 g_wkh[DD*DD],  g_wkl[DD*DD];
__device__ __nv_bfloat16 g_wvh[DD*DD],  g_wvl[DD*DD];
__device__ __nv_bfloat16 g_woh[DD*DD],  g_wol[DD*DD];
__device__ __nv_bfloat16 g_w1h[(size_t)DD*DFF], g_w1l[(size_t)DD*DFF];
__device__ __nv_bfloat16 g_w2h[(size_t)DD*DFF], g_w2l[(size_t)DD*DFF];

// ============================================================================
// PTX helpers (family-safe: ldmatrix / mma.sync / cp.async only)
// ============================================================================
__device__ __forceinline__ uint32_t smem_u32(const void* p) {
    uint32_t a;
    asm("{ .reg .u64 t; cvta.to.shared.u64 t, %1; cvt.u32.u64 %0, t; }"
        : "=r"(a) : "l"(p));
    return a;
}
__device__ __forceinline__ void ldsm4(uint32_t& r0, uint32_t& r1,
                                      uint32_t& r2, uint32_t& r3, uint32_t addr) {
    asm volatile("ldmatrix.sync.aligned.m8n8.x4.shared.b16 {%0,%1,%2,%3}, [%4];"
                 : "=r"(r0), "=r"(r1), "=r"(r2), "=r"(r3) : "r"(addr));
}
__device__ __forceinline__ void mma16816(float* c, const uint32_t* a, const uint32_t* b) {
    asm volatile(
        "mma.sync.aligned.m16n8k16.row.col.f32.bf16.bf16.f32 "
        "{%0,%1,%2,%3}, {%4,%5,%6,%7}, {%8,%9}, {%0,%1,%2,%3};"
        : "+f"(c[0]), "+f"(c[1]), "+f"(c[2]), "+f"(c[3])
        : "r"(a[0]), "r"(a[1]), "r"(a[2]), "r"(a[3]), "r"(b[0]), "r"(b[1]));
}
__device__ __forceinline__ void cp16(uint32_t dst, const void* src) {
    asm volatile("cp.async.cg.shared.global [%0], [%1], 16;" :: "r"(dst), "l"(src));
}
__device__ __forceinline__ void cp_commit() {
    asm volatile("cp.async.commit_group;" ::: "memory");
}
template<int N>
__device__ __forceinline__ void cp_wait() {
    asm volatile("cp.async.wait_group %0;" :: "n"(N) : "memory");
}

// ============================================================================
// Weight transpose + hi/lo bf16 split:  W[K,N] f32  ->  T[N,K] bf16 (h & l)
// ============================================================================
__global__ __launch_bounds__(256) void wsplit_kernel(
    const float* __restrict__ W, __nv_bfloat16* __restrict__ Th,
    __nv_bfloat16* __restrict__ Tl, int K, int N)
{
    __shared__ float t[32][33];
    const int tx = threadIdx.x, ty = threadIdx.y;
    const int n0 = blockIdx.x * 32, k0 = blockIdx.y * 32;
    #pragma unroll
    for (int i = 0; i < 32; i += 8)
        t[ty + i][tx] = W[(size_t)(k0 + ty + i) * N + n0 + tx];
    __syncthreads();
    #pragma unroll
    for (int i = 0; i < 32; i += 8) {
        float v = t[tx][ty + i];
        __nv_bfloat16 h = __float2bfloat16(v);
        float lo = v - __bfloat162float(h);
        size_t o = (size_t)(n0 + ty + i) * K + k0 + tx;
        Th[o] = h;
        Tl[o] = __float2bfloat16(lo);
    }
}

// ============================================================================
// LayerNorm (ddof=1, denom = std + eps), outputs hi/lo bf16 planes
// ============================================================================
__global__ __launch_bounds__(256) void ln_split_kernel(
    const float* __restrict__ x, const float* __restrict__ w,
    const float* __restrict__ b, __nv_bfloat16* __restrict__ oh,
    __nv_bfloat16* __restrict__ ol)
{
    const int row = blockIdx.x;
    const int tid = threadIdx.x;
    float4 v = ((const float4*)(x + (size_t)row * DD))[tid];

    float s  = v.x + v.y + v.z + v.w;
    float s2 = v.x*v.x + v.y*v.y + v.z*v.z + v.w*v.w;
    #pragma unroll
    for (int off = 16; off; off >>= 1) {
        s  += __shfl_xor_sync(0xffffffffu, s,  off);
        s2 += __shfl_xor_sync(0xffffffffu, s2, off);
    }
    __shared__ float rs[8], rs2[8];
    if ((tid & 31) == 0) { rs[tid >> 5] = s; rs2[tid >> 5] = s2; }
    __syncthreads();
    float ts = 0.f, ts2 = 0.f;
    #pragma unroll
    for (int i = 0; i < 8; i++) { ts += rs[i]; ts2 += rs2[i]; }

    const float mean = ts * (1.0f / (float)DD);
    float var = (ts2 - (float)DD * mean * mean) * (1.0f / (float)(DD - 1));
    var = fmaxf(var, 0.0f);
    const float inv = 1.0f / (sqrtf(var) + 1e-6f);

    float4 wv = ((const float4*)w)[tid];
    float4 bv = ((const float4*)b)[tid];
    float o[4];
    o[0] = wv.x * (v.x - mean) * inv + bv.x;
    o[1] = wv.y * (v.y - mean) * inv + bv.y;
    o[2] = wv.z * (v.z - mean) * inv + bv.z;
    o[3] = wv.w * (v.w - mean) * inv + bv.w;

    __nv_bfloat16 h[4], l[4];
    #pragma unroll
    for (int e = 0; e < 4; e++) {
        h[e] = __float2bfloat16(o[e]);
        l[e] = __float2bfloat16(o[e] - __bfloat162float(h[e]));
    }
    const size_t base = (size_t)row * DD + tid * 4;
    __nv_bfloat162 h01 = __halves2bfloat162(h[0], h[1]);
    __nv_bfloat162 h23 = __halves2bfloat162(h[2], h[3]);
    __nv_bfloat162 l01 = __halves2bfloat162(l[0], l[1]);
    __nv_bfloat162 l23 = __halves2bfloat162(l[2], l[3]);
    uint2 hu, lu;
    hu.x = *(uint32_t*)&h01; hu.y = *(uint32_t*)&h23;
    lu.x = *(uint32_t*)&l01; lu.y = *(uint32_t*)&l23;
    *(uint2*)(oh + base) = hu;
    *(uint2*)(ol + base) = lu;
}

// ============================================================================
// Split-bf16 GEMM on mma.sync (HMMA).  C[M,N] = epi(A @ B^T + bias)
//   A planes: [M,K] bf16 (hi, lo);  B planes: [N,K] bf16 (hi, lo)
//   Block 128x128, BK=32, 8 warps (2x4), warp tile 64x32.
//   3 products per k-step: AhBh + AhBl + AlBh, fp32 accumulate.
//   EPI: 0 = bias -> f32; 1 = bias+relu -> bf16 hi/lo; 2 = bias+resid -> f32
// ============================================================================
constexpr int PITCH  = 40;                 // bf16 per smem row (32 + 8 pad)
constexpr int PITCHB = PITCH * 2;          // 80 bytes
constexpr int PLANE  = 128 * PITCHB;       // 10240 B
constexpr int STAGE  = 4 * PLANE;          // 40960 B
constexpr int GSMEM  = 2 * STAGE;          // 81920 B

template<int EPI>
__global__ __launch_bounds__(256, 1) void mma_gemm(
    const __nv_bfloat16* __restrict__ Ah, const __nv_bfloat16* __restrict__ Al,
    const __nv_bfloat16* __restrict__ Bh, const __nv_bfloat16* __restrict__ Bl,
    const float* __restrict__ bias, const float* __restrict__ resid,
    float* __restrict__ Cf,
    __nv_bfloat16* __restrict__ Ch, __nv_bfloat16* __restrict__ Cl,
    int N, int K)
{
    extern __shared__ char sm[];
    const uint32_t base = smem_u32(sm);

    const int tid  = threadIdx.x;
    const int lane = tid & 31;
    const int wid  = tid >> 5;
    const int wr   = wid >> 2;      // 0..1 (64 rows each)
    const int wc   = wid & 3;       // 0..3 (32 cols each)
    const int row0 = blockIdx.y * 128;
    const int col0 = blockIdx.x * 128;

    const __nv_bfloat16* gA[4] = {
        Ah + (size_t)row0 * K, Al + (size_t)row0 * K,
        Bh + (size_t)col0 * K, Bl + (size_t)col0 * K };

    // prefetch one BK=32 stage into buffer st
    auto prefetch = [&](int st, int c) {
        const int k0 = c * 32;
        const uint32_t sb = base + st * STAGE;
        #pragma unroll
        for (int p = 0; p < 4; p++) {
            #pragma unroll
            for (int it = 0; it < 2; it++) {
                int idx = it * 256 + tid;
                int r = idx >> 2, ch = idx & 3;
                cp16(sb + p * PLANE + r * PITCHB + ch * 16,
                     gA[p] + (size_t)r * K + k0 + ch * 8);
            }
        }
        cp_commit();
    };

    float acc[4][4][4];
    #pragma unroll
    for (int i = 0; i < 4; i++)
        #pragma unroll
        for (int j = 0; j < 4; j++)
            #pragma unroll
            for (int e = 0; e < 4; e++) acc[i][j][e] = 0.0f;

    const int NC = K >> 5;
    prefetch(0, 0);

    // per-warp ldmatrix base offsets
    const uint32_t a_off = (uint32_t)((wr * 64 + (lane & 15)) * PITCHB + (lane >> 4) * 16);
    const uint32_t b_off = (uint32_t)((wc * 32 + (lane & 7) + ((lane >> 4) & 1) * 8) * PITCHB
                                      + ((lane >> 3) & 1) * 16);

    for (int c = 0; c < NC; c++) {
        if (c + 1 < NC) { prefetch((c + 1) & 1, c + 1); cp_wait<1>(); }
        else            { cp_wait<0>(); }
        __syncthreads();

        const uint32_t sb = base + (c & 1) * STAGE;
        const uint32_t aH = sb,             aL = sb + PLANE;
        const uint32_t bH = sb + 2 * PLANE, bL = sb + 3 * PLANE;

        #pragma unroll
        for (int ks = 0; ks < 2; ks++) {
            const uint32_t kb = ks * 32;   // 16 bf16 = 32 bytes
            uint32_t Af[4][4], Lf[4][4], Bf[4][2], Gf[4][2];

            #pragma unroll
            for (int i = 0; i < 4; i++)
                ldsm4(Af[i][0], Af[i][1], Af[i][2], Af[i][3],
                      aH + a_off + (uint32_t)(i * 16 * PITCHB) + kb);
            #pragma unroll
            for (int jj = 0; jj < 2; jj++)
                ldsm4(Bf[2*jj][0], Bf[2*jj][1], Bf[2*jj+1][0], Bf[2*jj+1][1],
                      bH + b_off + (uint32_t)(jj * 16 * PITCHB) + kb);
            #pragma unroll
            for (int i = 0; i < 4; i++)
                #pragma unroll
                for (int j = 0; j < 4; j++)
                    mma16816(acc[i][j], Af[i], Bf[j]);     // hi*hi

            #pragma unroll
            for (int jj = 0; jj < 2; jj++)
                ldsm4(Gf[2*jj][0], Gf[2*jj][1], Gf[2*jj+1][0], Gf[2*jj+1][1],
                      bL + b_off + (uint32_t)(jj * 16 * PITCHB) + kb);
            #pragma unroll
            for (int i = 0; i < 4; i++)
                #pragma unroll
                for (int j = 0; j < 4; j++)
                    mma16816(acc[i][j], Af[i], Gf[j]);     // hi*lo

            #pragma unroll
            for (int i = 0; i < 4; i++)
                ldsm4(Lf[i][0], Lf[i][1], Lf[i][2], Lf[i][3],
                      aL + a_off + (uint32_t)(i * 16 * PITCHB) + kb);
            #pragma unroll
            for (int i = 0; i < 4; i++)
                #pragma unroll
                for (int j = 0; j < 4; j++)
                    mma16816(acc[i][j], Lf[i], Bf[j]);     // lo*hi
        }
        __syncthreads();
    }

    // epilogue: direct stores from fragments
    #pragma unroll
    for (int i = 0; i < 4; i++) {
        const int m0 = row0 + wr * 64 + i * 16 + (lane >> 2);
        #pragma unroll
        for (int j = 0; j < 4; j++) {
            const int nb = col0 + wc * 32 + j * 8 + (lane & 3) * 2;
            const float2 bv = *(const float2*)(bias + nb);
            float c0 = acc[i][j][0] + bv.x, c1 = acc[i][j][1] + bv.y;
            float c2 = acc[i][j][2] + bv.x, c3 = acc[i][j][3] + bv.y;
            const size_t o0 = (size_t)m0 * N + nb;
            const size_t o1 = (size_t)(m0 + 8) * N + nb;
            if (EPI == 2) {
                float2 r0 = *(const float2*)(resid + o0);
                float2 r1 = *(const float2*)(resid + o1);
                c0 += r0.x; c1 += r0.y; c2 += r1.x; c3 += r1.y;
            }
            if (EPI == 1) {
                c0 = fmaxf(c0, 0.f); c1 = fmaxf(c1, 0.f);
                c2 = fmaxf(c2, 0.f); c3 = fmaxf(c3, 0.f);
                float a[4] = {c0, c1, c2, c3};
                __nv_bfloat16 h[4], l[4];
                #pragma unroll
                for (int e = 0; e < 4; e++) {
                    h[e] = __float2bfloat16(a[e]);
                    l[e] = __float2bfloat16(a[e] - __bfloat162float(h[e]));
                }
                __nv_bfloat162 h01 = __halves2bfloat162(h[0], h[1]);
                __nv_bfloat162 h23 = __halves2bfloat162(h[2], h[3]);
                __nv_bfloat162 l01 = __halves2bfloat162(l[0], l[1]);
                __nv_bfloat162 l23 = __halves2bfloat162(l[2], l[3]);
                *(uint32_t*)(Ch + o0) = *(uint32_t*)&h01;
                *(uint32_t*)(Ch + o1) = *(uint32_t*)&h23;
                *(uint32_t*)(Cl + o0) = *(uint32_t*)&l01;
                *(uint32_t*)(Cl + o1) = *(uint32_t*)&l23;
            } else {
                *(float2*)(Cf + o0) = make_float2(c0, c1);
                *(float2*)(Cf + o1) = make_float2(c2, c3);
            }
        }
    }
}

// ============================================================================
// Flash attention (fp32, online softmax), outputs hi/lo bf16 planes
// ============================================================================
constexpr int FPITCH = 68;
constexpr int FLASH_SMEM = 4 * 64 * FPITCH * 4 + 64 * 4;

__global__ __launch_bounds__(256) void flash_kernel(
    const float* __restrict__ q, const float* __restrict__ k,
    const float* __restrict__ v, const int* __restrict__ mask,
    __nv_bfloat16* __restrict__ oh, __nv_bfloat16* __restrict__ ol)
{
    extern __shared__ float smf[];
    float* Qt = smf;
    float* Kt = smf + 64 * FPITCH;
    float* Vs = smf + 2 * 64 * FPITCH;
    float* Pt = smf + 3 * 64 * FPITCH;
    int*  msk = (int*)(smf + 4 * 64 * FPITCH);

    const int tid = threadIdx.x;
    const int b = blockIdx.z, h = blockIdx.y;
    const int q0 = blockIdx.x * 64;
    const int tx = tid & 15, ty = tid >> 4;
    const int r0 = ty << 2, c0 = tx << 2;

    {
        const float* qb = q + ((size_t)(b * SS + q0)) * DD + h * DK;
        #pragma unroll
        for (int it = 0; it < 16; it++) {
            int idx = it * 256 + tid;
            int r = idx >> 6, d = idx & 63;
            Qt[d * FPITCH + r] = qb[(size_t)r * DD + d];
        }
    }

    float o[4][4];
    #pragma unroll
    for (int i = 0; i < 4; i++)
        #pragma unroll
        for (int j = 0; j < 4; j++) o[i][j] = 0.0f;
    float mrow[4], lrow[4];
    #pragma unroll
    for (int i = 0; i < 4; i++) { mrow[i] = -INFINITY; lrow[i] = 0.0f; }

    for (int kt = 0; kt < SS; kt += 64) {
        const float* kb = k + ((size_t)(b * SS + kt)) * DD + h * DK;
        const float* vb = v + ((size_t)(b * SS + kt)) * DD + h * DK;
        #pragma unroll
        for (int it = 0; it < 16; it++) {
            int idx = it * 256 + tid;
            int r = idx >> 6, d = idx & 63;
            Kt[d * FPITCH + r] = kb[(size_t)r * DD + d];
            Vs[r * FPITCH + d] = vb[(size_t)r * DD + d];
        }
        if (tid < 64) msk[tid] = mask[(size_t)b * SS + kt + tid];
        __syncthreads();

        float s[4][4];
        #pragma unroll
        for (int i = 0; i < 4; i++)
            #pragma unroll
            for (int j = 0; j < 4; j++) s[i][j] = 0.0f;
        #pragma unroll 8
        for (int d = 0; d < 64; d++) {
            float4 a  = *(const float4*)&Qt[d * FPITCH + r0];
            float4 bb = *(const float4*)&Kt[d * FPITCH + c0];
            const float af[4] = {a.x, a.y, a.z, a.w};
            const float bf[4] = {bb.x, bb.y, bb.z, bb.w};
            #pragma unroll
            for (int i = 0; i < 4; i++)
                #pragma unroll
                for (int j = 0; j < 4; j++)
                    s[i][j] = fmaf(af[i], bf[j], s[i][j]);
        }

        #pragma unroll
        for (int i = 0; i < 4; i++) {
            float sj[4];
            #pragma unroll
            for (int j = 0; j < 4; j++) {
                float t = s[i][j] * 0.125f;
                sj[j] = (msk[c0 + j] == 0) ? -INFINITY : t;
            }
            float mx = fmaxf(fmaxf(sj[0], sj[1]), fmaxf(sj[2], sj[3]));
            #pragma unroll
            for (int off = 8; off; off >>= 1)
                mx = fmaxf(mx, __shfl_xor_sync(0xffffffffu, mx, off, 16));
            float mnew  = fmaxf(mrow[i], mx);
            float alpha = __expf(mrow[i] - mnew);
            float p[4], rsum = 0.0f;
            #pragma unroll
            for (int j = 0; j < 4; j++) { p[j] = __expf(sj[j] - mnew); rsum += p[j]; }
            #pragma unroll
            for (int off = 8; off; off >>= 1)
                rsum += __shfl_xor_sync(0xffffffffu, rsum, off, 16);
            lrow[i] = lrow[i] * alpha + rsum;
            mrow[i] = mnew;
            #pragma unroll
            for (int d = 0; d < 4; d++) o[i][d] *= alpha;
            #pragma unroll
            for (int j = 0; j < 4; j++) Pt[(c0 + j) * FPITCH + r0 + i] = p[j];
        }
        __syncthreads();

        #pragma unroll 8
        for (int j = 0; j < 64; j++) {
            float4 a  = *(const float4*)&Pt[j * FPITCH + r0];
            float4 vv = *(const float4*)&Vs[j * FPITCH + c0];
            const float af[4] = {a.x, a.y, a.z, a.w};
            const float vf[4] = {vv.x, vv.y, vv.z, vv.w};
            #pragma unroll
            for (int i = 0; i < 4; i++)
                #pragma unroll
                for (int d = 0; d < 4; d++)
                    o[i][d] = fmaf(af[i], vf[d], o[i][d]);
        }
        __syncthreads();
    }

    #pragma unroll
    for (int i = 0; i < 4; i++) {
        float inv = 1.0f / lrow[i];
        float a[4] = {o[i][0]*inv, o[i][1]*inv, o[i][2]*inv, o[i][3]*inv};
        __nv_bfloat16 hh[4], ll[4];
        #pragma unroll
        for (int e = 0; e < 4; e++) {
            hh[e] = __float2bfloat16(a[e]);
            ll[e] = __float2bfloat16(a[e] - __bfloat162float(hh[e]));
        }
        const size_t base = ((size_t)(b * SS + q0 + r0 + i)) * DD + h * DK + c0;
        __nv_bfloat162 h01 = __halves2bfloat162(hh[0], hh[1]);
        __nv_bfloat162 h23 = __halves2bfloat162(hh[2], hh[3]);
        __nv_bfloat162 l01 = __halves2bfloat162(ll[0], ll[1]);
        __nv_bfloat162 l23 = __halves2bfloat162(ll[2], ll[3]);
        uint2 hu, lu;
        hu.x = *(uint32_t*)&h01; hu.y = *(uint32_t*)&h23;
        lu.x = *(uint32_t*)&l01; lu.y = *(uint32_t*)&l23;
        *(uint2*)(oh + base) = hu;
        *(uint2*)(ol + base) = lu;
    }
}

// ============================================================================
// kernel_launch
// ============================================================================
extern "C" void kernel_launch(void* const* d_in, const int* in_sizes, int n_in,
                              void* d_out, int out_size)
{
    const float* x    = (const float*)d_in[0];
    const int*   mask = (const int*)  d_in[1];
    const float* wq   = (const float*)d_in[2];
    const float* bq   = (const float*)d_in[3];
    const float* wk   = (const float*)d_in[4];
    const float* bk   = (const float*)d_in[5];
    const float* wv   = (const float*)d_in[6];
    const float* bv   = (const float*)d_in[7];
    const float* wo   = (const float*)d_in[8];
    const float* bo   = (const float*)d_in[9];
    const float* w1   = (const float*)d_in[10];
    const float* b1   = (const float*)d_in[11];
    const float* w2   = (const float*)d_in[12];
    const float* b2   = (const float*)d_in[13];
    const float* ln1w = (const float*)d_in[14];
    const float* ln1b = (const float*)d_in[15];
    const float* ln2w = (const float*)d_in[16];
    const float* ln2b = (const float*)d_in[17];
    float* out = (float*)d_out;

    __nv_bfloat16 *xnh, *xnl, *ath, *atl, *ffh, *ffl;
    __nv_bfloat16 *wqh, *wql, *wkh, *wkl, *wvh, *wvl, *woh, *wol, *w1h, *w1l, *w2h, *w2l;
    float *qq, *kk, *vv;
    cudaGetSymbolAddress((void**)&xnh, g_xnh);  cudaGetSymbolAddress((void**)&xnl, g_xnl);
    cudaGetSymbolAddress((void**)&qq,  g_q);    cudaGetSymbolAddress((void**)&kk,  g_k);
    cudaGetSymbolAddress((void**)&vv,  g_v);
    cudaGetSymbolAddress((void**)&ath, g_ath);  cudaGetSymbolAddress((void**)&atl, g_atl);
    cudaGetSymbolAddress((void**)&ffh, g_ffh);  cudaGetSymbolAddress((void**)&ffl, g_ffl);
    cudaGetSymbolAddress((void**)&wqh, g_wqh);  cudaGetSymbolAddress((void**)&wql, g_wql);
    cudaGetSymbolAddress((void**)&wkh, g_wkh);  cudaGetSymbolAddress((void**)&wkl, g_wkl);
    cudaGetSymbolAddress((void**)&wvh, g_wvh);  cudaGetSymbolAddress((void**)&wvl, g_wvl);
    cudaGetSymbolAddress((void**)&woh, g_woh);  cudaGetSymbolAddress((void**)&wol, g_wol);
    cudaGetSymbolAddress((void**)&w1h, g_w1h);  cudaGetSymbolAddress((void**)&w1l, g_w1l);
    cudaGetSymbolAddress((void**)&w2h, g_w2h);  cudaGetSymbolAddress((void**)&w2l, g_w2l);

    cudaFuncSetAttribute(flash_kernel,
                         cudaFuncAttributeMaxDynamicSharedMemorySize, FLASH_SMEM);
    cudaFuncSetAttribute(mma_gemm<0>,
                         cudaFuncAttributeMaxDynamicSharedMemorySize, GSMEM);
    cudaFuncSetAttribute(mma_gemm<1>,
                         cudaFuncAttributeMaxDynamicSharedMemorySize, GSMEM);
    cudaFuncSetAttribute(mma_gemm<2>,
                         cudaFuncAttributeMaxDynamicSharedMemorySize, GSMEM);

    dim3 tb(32, 8);
    // weight transpose + split  (W[K,N] -> T[N,K] hi/lo)
    wsplit_kernel<<<dim3(DD/32,  DD/32),  tb>>>(wq, wqh, wql, DD, DD);
    wsplit_kernel<<<dim3(DD/32,  DD/32),  tb>>>(wk, wkh, wkl, DD, DD);
    wsplit_kernel<<<dim3(DD/32,  DD/32),  tb>>>(wv, wvh, wvl, DD, DD);
    wsplit_kernel<<<dim3(DD/32,  DD/32),  tb>>>(wo, woh, wol, DD, DD);
    wsplit_kernel<<<dim3(DFF/32, DD/32),  tb>>>(w1, w1h, w1l, DD, DFF);
    wsplit_kernel<<<dim3(DD/32,  DFF/32), tb>>>(w2, w2h, w2l, DFF, DD);

    // 1. ln1 -> hi/lo planes
    ln_split_kernel<<<MM, 256>>>(x, ln1w, ln1b, xnh, xnl);

    // 2-4. Q, K, V projections  (M=8192, N=1024, K=1024), fp32 out
    dim3 g1(DD / 128, MM / 128);
    mma_gemm<0><<<g1, 256, GSMEM>>>(xnh, xnl, wqh, wql, bq, nullptr, qq, nullptr, nullptr, DD, DD);
    mma_gemm<0><<<g1, 256, GSMEM>>>(xnh, xnl, wkh, wkl, bk, nullptr, kk, nullptr, nullptr, DD, DD);
    mma_gemm<0><<<g1, 256, GSMEM>>>(xnh, xnl, wvh, wvl, bv, nullptr, vv, nullptr, nullptr, DD, DD);

    // 5. attention -> hi/lo planes
    dim3 gf(SS / 64, HH, BB);
    flash_kernel<<<gf, 256, FLASH_SMEM>>>(qq, kk, vv, mask, ath, atl);

    // 6. O projection + residual -> h1 (fp32) in d_out
    mma_gemm<2><<<g1, 256, GSMEM>>>(ath, atl, woh, wol, bo, x, out, nullptr, nullptr, DD, DD);

    // 7. ln2 -> hi/lo planes
    ln_split_kernel<<<MM, 256>>>(out, ln2w, ln2b, xnh, xnl);

    // 8. FFN up + relu  (N=4096) -> hi/lo planes
    dim3 g2(DFF / 128, MM / 128);
    mma_gemm<1><<<g2, 256, GSMEM>>>(xnh, xnl, w1h, w1l, b1, nullptr, nullptr, ffh, ffl, DFF, DD);

    // 9. FFN down + residual  (K=4096), fp32 out (in-place on d_out)
    mma_gemm<2><<<g1, 256, GSMEM>>>(ffh, ffl, w2h, w2l, b2, out, out, nullptr, nullptr, DD, DFF);
}

// round 12
// speedup vs baseline: 2.5829x; 1.5170x over previous
#include <cuda_runtime.h>
#include <cuda_bf16.h>
#include <math.h>
#include <stdint.h>

// Problem constants
constexpr int BB  = 4;
constexpr int SS  = 2048;
constexpr int DD  = 1024;
constexpr int HH  = 16;
constexpr int DK  = 64;
constexpr int DFF = 4096;
constexpr int MM  = BB * SS;           // 8192 rows

// ---------------- scratch (device globals; allocation is forbidden) --------
__device__ __nv_bfloat16 g_xnh [(size_t)MM * DD];
__device__ __nv_bfloat16 g_xnl [(size_t)MM * DD];
__device__ __nv_bfloat16 g_qh  [(size_t)MM * DD];
__device__ __nv_bfloat16 g_ql  [(size_t)MM * DD];
__device__ __nv_bfloat16 g_kh  [(size_t)MM * DD];
__device__ __nv_bfloat16 g_kl  [(size_t)MM * DD];
__device__ __nv_bfloat16 g_vh  [(size_t)MM * DD];
__device__ __nv_bfloat16 g_vl  [(size_t)MM * DD];
__device__ __nv_bfloat16 g_ath [(size_t)MM * DD];
__device__ __nv_bfloat16 g_atl [(size_t)MM * DD];
__device__ __nv_bfloat16 g_ffh [(size_t)MM * DFF];
__device__ __nv_bfloat16 g_ffl [(size_t)MM * DFF];
// transposed + split weights: [N,K] K-major bf16
__device__ __nv_bfloat16 g_wqh[DD*DD],  g_wql[DD*DD];
__device__ __nv_bfloat16 g_wkh[DD*DD],  g_wkl[DD*DD];
__device__ __nv_bfloat16 g_wvh[DD*DD],  g_wvl[DD*DD];
__device__ __nv_bfloat16 g_woh[DD*DD],  g_wol[DD*DD];
__device__ __nv_bfloat16 g_w1h[(size_t)DD*DFF], g_w1l[(size_t)DD*DFF];
__device__ __nv_bfloat16 g_w2h[(size_t)DD*DFF], g_w2l[(size_t)DD*DFF];

// ============================================================================
// PTX helpers (family-safe: ldmatrix / mma.sync / cp.async only)
// ============================================================================
__device__ __forceinline__ uint32_t smem_u32(const void* p) {
    uint32_t a;
    asm("{ .reg .u64 t; cvta.to.shared.u64 t, %1; cvt.u32.u64 %0, t; }"
        : "=r"(a) : "l"(p));
    return a;
}
__device__ __forceinline__ void ldsm4(uint32_t& r0, uint32_t& r1,
                                      uint32_t& r2, uint32_t& r3, uint32_t addr) {
    asm volatile("ldmatrix.sync.aligned.m8n8.x4.shared.b16 {%0,%1,%2,%3}, [%4];"
                 : "=r"(r0), "=r"(r1), "=r"(r2), "=r"(r3) : "r"(addr));
}
__device__ __forceinline__ void ldsm4t(uint32_t& r0, uint32_t& r1,
                                       uint32_t& r2, uint32_t& r3, uint32_t addr) {
    asm volatile("ldmatrix.sync.aligned.m8n8.x4.trans.shared.b16 {%0,%1,%2,%3}, [%4];"
                 : "=r"(r0), "=r"(r1), "=r"(r2), "=r"(r3) : "r"(addr));
}
__device__ __forceinline__ void mma16816(float* c, const uint32_t* a, const uint32_t* b) {
    asm volatile(
        "mma.sync.aligned.m16n8k16.row.col.f32.bf16.bf16.f32 "
        "{%0,%1,%2,%3}, {%4,%5,%6,%7}, {%8,%9}, {%0,%1,%2,%3};"
        : "+f"(c[0]), "+f"(c[1]), "+f"(c[2]), "+f"(c[3])
        : "r"(a[0]), "r"(a[1]), "r"(a[2]), "r"(a[3]), "r"(b[0]), "r"(b[1]));
}
__device__ __forceinline__ void cp16(uint32_t dst, const void* src) {
    asm volatile("cp.async.cg.shared.global [%0], [%1], 16;" :: "r"(dst), "l"(src));
}
__device__ __forceinline__ void cp_commit() {
    asm volatile("cp.async.commit_group;" ::: "memory");
}
template<int N>
__device__ __forceinline__ void cp_wait() {
    asm volatile("cp.async.wait_group %0;" :: "n"(N) : "memory");
}
__device__ __forceinline__ uint32_t pack_bf16(float a, float b) {
    __nv_bfloat162 t = __floats2bfloat162_rn(a, b);   // .x = a (low), .y = b (high)
    return *(uint32_t*)&t;
}

// ============================================================================
// Weight transpose + hi/lo bf16 split:  W[K,N] f32  ->  T[N,K] bf16 (h & l)
// ============================================================================
__global__ __launch_bounds__(256) void wsplit_kernel(
    const float* __restrict__ W, __nv_bfloat16* __restrict__ Th,
    __nv_bfloat16* __restrict__ Tl, int K, int N)
{
    __shared__ float t[32][33];
    const int tx = threadIdx.x, ty = threadIdx.y;
    const int n0 = blockIdx.x * 32, k0 = blockIdx.y * 32;
    #pragma unroll
    for (int i = 0; i < 32; i += 8)
        t[ty + i][tx] = W[(size_t)(k0 + ty + i) * N + n0 + tx];
    __syncthreads();
    #pragma unroll
    for (int i = 0; i < 32; i += 8) {
        float v = t[tx][ty + i];
        __nv_bfloat16 h = __float2bfloat16(v);
        float lo = v - __bfloat162float(h);
        size_t o = (size_t)(n0 + ty + i) * K + k0 + tx;
        Th[o] = h;
        Tl[o] = __float2bfloat16(lo);
    }
}

// ============================================================================
// LayerNorm (ddof=1, denom = std + eps), outputs hi/lo bf16 planes
// ============================================================================
__global__ __launch_bounds__(256) void ln_split_kernel(
    const float* __restrict__ x, const float* __restrict__ w,
    const float* __restrict__ b, __nv_bfloat16* __restrict__ oh,
    __nv_bfloat16* __restrict__ ol)
{
    const int row = blockIdx.x;
    const int tid = threadIdx.x;
    float4 v = ((const float4*)(x + (size_t)row * DD))[tid];

    float s  = v.x + v.y + v.z + v.w;
    float s2 = v.x*v.x + v.y*v.y + v.z*v.z + v.w*v.w;
    #pragma unroll
    for (int off = 16; off; off >>= 1) {
        s  += __shfl_xor_sync(0xffffffffu, s,  off);
        s2 += __shfl_xor_sync(0xffffffffu, s2, off);
    }
    __shared__ float rs[8], rs2[8];
    if ((tid & 31) == 0) { rs[tid >> 5] = s; rs2[tid >> 5] = s2; }
    __syncthreads();
    float ts = 0.f, ts2 = 0.f;
    #pragma unroll
    for (int i = 0; i < 8; i++) { ts += rs[i]; ts2 += rs2[i]; }

    const float mean = ts * (1.0f / (float)DD);
    float var = (ts2 - (float)DD * mean * mean) * (1.0f / (float)(DD - 1));
    var = fmaxf(var, 0.0f);
    const float inv = 1.0f / (sqrtf(var) + 1e-6f);

    float4 wv = ((const float4*)w)[tid];
    float4 bv = ((const float4*)b)[tid];
    float o[4];
    o[0] = wv.x * (v.x - mean) * inv + bv.x;
    o[1] = wv.y * (v.y - mean) * inv + bv.y;
    o[2] = wv.z * (v.z - mean) * inv + bv.z;
    o[3] = wv.w * (v.w - mean) * inv + bv.w;

    __nv_bfloat16 h[4], l[4];
    #pragma unroll
    for (int e = 0; e < 4; e++) {
        h[e] = __float2bfloat16(o[e]);
        l[e] = __float2bfloat16(o[e] - __bfloat162float(h[e]));
    }
    const size_t base = (size_t)row * DD + tid * 4;
    uint2 hu, lu;
    hu.x = pack_bf16(o[0] - 0.f, 0.f);  // placeholder overwritten below
    __nv_bfloat162 h01 = __halves2bfloat162(h[0], h[1]);
    __nv_bfloat162 h23 = __halves2bfloat162(h[2], h[3]);
    __nv_bfloat162 l01 = __halves2bfloat162(l[0], l[1]);
    __nv_bfloat162 l23 = __halves2bfloat162(l[2], l[3]);
    hu.x = *(uint32_t*)&h01; hu.y = *(uint32_t*)&h23;
    lu.x = *(uint32_t*)&l01; lu.y = *(uint32_t*)&l23;
    *(uint2*)(oh + base) = hu;
    *(uint2*)(ol + base) = lu;
}

// ============================================================================
// Split-bf16 GEMM on mma.sync (HMMA).  C[M,N] = epi(A @ B^T + bias)
//   EPI: 0 = bias -> f32; 1 = bias+relu -> bf16 hi/lo; 2 = bias+resid -> f32
//        3 = bias -> bf16 hi/lo
// ============================================================================
constexpr int PITCH  = 40;                 // bf16 per smem row (32 + 8 pad)
constexpr int PITCHB = PITCH * 2;          // 80 bytes
constexpr int PLANE  = 128 * PITCHB;       // 10240 B
constexpr int STAGE  = 4 * PLANE;          // 40960 B
constexpr int GSMEM  = 2 * STAGE;          // 81920 B

template<int EPI>
__global__ __launch_bounds__(256, 1) void mma_gemm(
    const __nv_bfloat16* __restrict__ Ah, const __nv_bfloat16* __restrict__ Al,
    const __nv_bfloat16* __restrict__ Bh, const __nv_bfloat16* __restrict__ Bl,
    const float* __restrict__ bias, const float* __restrict__ resid,
    float* __restrict__ Cf,
    __nv_bfloat16* __restrict__ Ch, __nv_bfloat16* __restrict__ Cl,
    int N, int K)
{
    extern __shared__ char sm[];
    const uint32_t base = smem_u32(sm);

    const int tid  = threadIdx.x;
    const int lane = tid & 31;
    const int wid  = tid >> 5;
    const int wr   = wid >> 2;      // 0..1 (64 rows each)
    const int wc   = wid & 3;       // 0..3 (32 cols each)
    const int row0 = blockIdx.y * 128;
    const int col0 = blockIdx.x * 128;

    const __nv_bfloat16* gA[4] = {
        Ah + (size_t)row0 * K, Al + (size_t)row0 * K,
        Bh + (size_t)col0 * K, Bl + (size_t)col0 * K };

    auto prefetch = [&](int st, int c) {
        const int k0 = c * 32;
        const uint32_t sb = base + st * STAGE;
        #pragma unroll
        for (int p = 0; p < 4; p++) {
            #pragma unroll
            for (int it = 0; it < 2; it++) {
                int idx = it * 256 + tid;
                int r = idx >> 2, ch = idx & 3;
                cp16(sb + p * PLANE + r * PITCHB + ch * 16,
                     gA[p] + (size_t)r * K + k0 + ch * 8);
            }
        }
        cp_commit();
    };

    float acc[4][4][4];
    #pragma unroll
    for (int i = 0; i < 4; i++)
        #pragma unroll
        for (int j = 0; j < 4; j++)
            #pragma unroll
            for (int e = 0; e < 4; e++) acc[i][j][e] = 0.0f;

    const int NC = K >> 5;
    prefetch(0, 0);

    const uint32_t a_off = (uint32_t)((wr * 64 + (lane & 15)) * PITCHB + (lane >> 4) * 16);
    const uint32_t b_off = (uint32_t)((wc * 32 + (lane & 7) + ((lane >> 4) & 1) * 8) * PITCHB
                                      + ((lane >> 3) & 1) * 16);

    for (int c = 0; c < NC; c++) {
        if (c + 1 < NC) { prefetch((c + 1) & 1, c + 1); cp_wait<1>(); }
        else            { cp_wait<0>(); }
        __syncthreads();

        const uint32_t sb = base + (c & 1) * STAGE;
        const uint32_t aH = sb,             aL = sb + PLANE;
        const uint32_t bH = sb + 2 * PLANE, bL = sb + 3 * PLANE;

        #pragma unroll
        for (int ks = 0; ks < 2; ks++) {
            const uint32_t kb = ks * 32;
            uint32_t Af[4][4], Lf[4][4], Bf[4][2], Gf[4][2];

            #pragma unroll
            for (int i = 0; i < 4; i++)
                ldsm4(Af[i][0], Af[i][1], Af[i][2], Af[i][3],
                      aH + a_off + (uint32_t)(i * 16 * PITCHB) + kb);
            #pragma unroll
            for (int jj = 0; jj < 2; jj++)
                ldsm4(Bf[2*jj][0], Bf[2*jj][1], Bf[2*jj+1][0], Bf[2*jj+1][1],
                      bH + b_off + (uint32_t)(jj * 16 * PITCHB) + kb);
            #pragma unroll
            for (int i = 0; i < 4; i++)
                #pragma unroll
                for (int j = 0; j < 4; j++)
                    mma16816(acc[i][j], Af[i], Bf[j]);     // hi*hi

            #pragma unroll
            for (int jj = 0; jj < 2; jj++)
                ldsm4(Gf[2*jj][0], Gf[2*jj][1], Gf[2*jj+1][0], Gf[2*jj+1][1],
                      bL + b_off + (uint32_t)(jj * 16 * PITCHB) + kb);
            #pragma unroll
            for (int i = 0; i < 4; i++)
                #pragma unroll
                for (int j = 0; j < 4; j++)
                    mma16816(acc[i][j], Af[i], Gf[j]);     // hi*lo

            #pragma unroll
            for (int i = 0; i < 4; i++)
                ldsm4(Lf[i][0], Lf[i][1], Lf[i][2], Lf[i][3],
                      aL + a_off + (uint32_t)(i * 16 * PITCHB) + kb);
            #pragma unroll
            for (int i = 0; i < 4; i++)
                #pragma unroll
                for (int j = 0; j < 4; j++)
                    mma16816(acc[i][j], Lf[i], Bf[j]);     // lo*hi
        }
        __syncthreads();
    }

    // epilogue: direct stores from fragments
    #pragma unroll
    for (int i = 0; i < 4; i++) {
        const int m0 = row0 + wr * 64 + i * 16 + (lane >> 2);
        #pragma unroll
        for (int j = 0; j < 4; j++) {
            const int nb = col0 + wc * 32 + j * 8 + (lane & 3) * 2;
            const float2 bv = *(const float2*)(bias + nb);
            float c0 = acc[i][j][0] + bv.x, c1 = acc[i][j][1] + bv.y;
            float c2 = acc[i][j][2] + bv.x, c3 = acc[i][j][3] + bv.y;
            const size_t o0 = (size_t)m0 * N + nb;
            const size_t o1 = (size_t)(m0 + 8) * N + nb;
            if (EPI == 2) {
                float2 r0 = *(const float2*)(resid + o0);
                float2 r1 = *(const float2*)(resid + o1);
                c0 += r0.x; c1 += r0.y; c2 += r1.x; c3 += r1.y;
            }
            if (EPI == 1 || EPI == 3) {
                if (EPI == 1) {
                    c0 = fmaxf(c0, 0.f); c1 = fmaxf(c1, 0.f);
                    c2 = fmaxf(c2, 0.f); c3 = fmaxf(c3, 0.f);
                }
                float a[4] = {c0, c1, c2, c3};
                __nv_bfloat16 h[4], l[4];
                #pragma unroll
                for (int e = 0; e < 4; e++) {
                    h[e] = __float2bfloat16(a[e]);
                    l[e] = __float2bfloat16(a[e] - __bfloat162float(h[e]));
                }
                __nv_bfloat162 h01 = __halves2bfloat162(h[0], h[1]);
                __nv_bfloat162 h23 = __halves2bfloat162(h[2], h[3]);
                __nv_bfloat162 l01 = __halves2bfloat162(l[0], l[1]);
                __nv_bfloat162 l23 = __halves2bfloat162(l[2], l[3]);
                *(uint32_t*)(Ch + o0) = *(uint32_t*)&h01;
                *(uint32_t*)(Ch + o1) = *(uint32_t*)&h23;
                *(uint32_t*)(Cl + o0) = *(uint32_t*)&l01;
                *(uint32_t*)(Cl + o1) = *(uint32_t*)&l23;
            } else {
                *(float2*)(Cf + o0) = make_float2(c0, c1);
                *(float2*)(Cf + o1) = make_float2(c2, c3);
            }
        }
    }
}

// ============================================================================
// Flash attention on mma.sync, split-bf16 for QK^T and PV, online softmax.
// Block = 128 queries x one (b,h). 8 warps x 16 query rows. Key tiles of 64.
// smem: K/V hi/lo tiles, pitch 144B (72 bf16) -> conflict-free ldmatrix.
// ============================================================================
constexpr int FPB    = 144;            // bytes per 64-dk row in smem
constexpr int FPLANE = 64 * FPB;       // 9216 B (64 keys)
constexpr int FSTAGE = 4 * FPLANE;     // Kh,Kl,Vh,Vl = 36864 B
constexpr int FMSK   = 2 * FSTAGE;     // mask area offset
constexpr int FSMEM  = 2 * FSTAGE + 512;
constexpr float SCL  = 0.125f;         // 1/sqrt(64)

__global__ __launch_bounds__(256, 1) void flash_mma(
    const __nv_bfloat16* __restrict__ qh, const __nv_bfloat16* __restrict__ ql,
    const __nv_bfloat16* __restrict__ kh, const __nv_bfloat16* __restrict__ kl,
    const __nv_bfloat16* __restrict__ vh, const __nv_bfloat16* __restrict__ vl,
    const int* __restrict__ mask,
    __nv_bfloat16* __restrict__ oh, __nv_bfloat16* __restrict__ ol)
{
    extern __shared__ char sm[];
    const uint32_t base = smem_u32(sm);

    const int tid  = threadIdx.x;
    const int lane = tid & 31;
    const int wrp  = tid >> 5;
    const int b = blockIdx.z, h = blockIdx.y;
    const int q0 = blockIdx.x * 128;

    const size_t bh_off = (size_t)(b * SS) * DD + h * DK;
    const __nv_bfloat16* gp[4] = { kh + bh_off, kl + bh_off,
                                   vh + bh_off, vl + bh_off };
    const int* mask_p = mask + (size_t)b * SS;

    // ---- load Q tile (128 rows x 64 dk, hi/lo) via stage0 area ----
    {
        const __nv_bfloat16* qp[2] = { qh + bh_off + (size_t)q0 * DD,
                                       ql + bh_off + (size_t)q0 * DD };
        #pragma unroll
        for (int p = 0; p < 2; p++) {
            #pragma unroll
            for (int it = 0; it < 4; it++) {
                int rem = it * 256 + tid;
                int row = rem >> 3, ch = rem & 7;
                cp16(base + p * (128 * FPB) + row * FPB + ch * 16,
                     qp[p] + (size_t)row * DD + ch * 8);
            }
        }
        cp_commit();
        cp_wait<0>();
        __syncthreads();
    }

    uint32_t Qh4[4][4], Ql4[4][4];
    {
        const uint32_t qoff = (uint32_t)((16 * wrp + (lane & 15)) * FPB + (lane >> 4) * 16);
        #pragma unroll
        for (int ks = 0; ks < 4; ks++) {
            ldsm4(Qh4[ks][0], Qh4[ks][1], Qh4[ks][2], Qh4[ks][3],
                  base + qoff + ks * 32);
            ldsm4(Ql4[ks][0], Ql4[ks][1], Ql4[ks][2], Ql4[ks][3],
                  base + 128 * FPB + qoff + ks * 32);
        }
    }
    __syncthreads();   // done with Q staging area before K/V prefetch reuses it

    auto prefetch = [&](int st, int t) {
        const int key0 = t * 64;
        const uint32_t sb = base + st * FSTAGE;
        #pragma unroll
        for (int p = 0; p < 4; p++) {
            #pragma unroll
            for (int half = 0; half < 2; half++) {
                int rem = half * 256 + tid;
                int row = rem >> 3, ch = rem & 7;
                cp16(sb + p * FPLANE + row * FPB + ch * 16,
                     gp[p] + (size_t)(key0 + row) * DD + ch * 8);
            }
        }
        if (tid < 16)
            cp16(base + FMSK + st * 256 + tid * 16, mask_p + key0 + tid * 4);
        cp_commit();
    };

    float oacc[8][4];
    #pragma unroll
    for (int nt = 0; nt < 8; nt++)
        #pragma unroll
        for (int e = 0; e < 4; e++) oacc[nt][e] = 0.0f;
    float m0 = -1e30f, m1 = -1e30f, l0 = 0.0f, l1 = 0.0f;

    const uint32_t boff = (uint32_t)(((lane & 7) + ((lane >> 4) & 1) * 8) * FPB
                                     + ((lane >> 3) & 1) * 16);
    const uint32_t voff = (uint32_t)(((lane & 7) + ((lane >> 3) & 1) * 8) * FPB
                                     + ((lane >> 4) & 1) * 16);
    const int cbase = (lane & 3) * 2;

    constexpr int NT = SS / 64;   // 32 key tiles
    prefetch(0, 0);

    for (int c = 0; c < NT; c++) {
        if (c + 1 < NT) { prefetch((c + 1) & 1, c + 1); cp_wait<1>(); }
        else            { cp_wait<0>(); }
        __syncthreads();

        const uint32_t sb = base + (c & 1) * FSTAGE;
        const int* mk = (const int*)(sm + (FMSK - (base - base)) ) + 0; // see below
        const int* mks = (const int*)(sm + FMSK + (c & 1) * 256);

        // ---- S = Q K^T (split, scaled later) ----
        float sacc[8][4];
        #pragma unroll
        for (int nt = 0; nt < 8; nt++)
            #pragma unroll
            for (int e = 0; e < 4; e++) sacc[nt][e] = 0.0f;

        #pragma unroll
        for (int ks = 0; ks < 4; ks++) {
            uint32_t KH[8][2], KL[8][2];
            #pragma unroll
            for (int jj = 0; jj < 4; jj++)
                ldsm4(KH[2*jj][0], KH[2*jj][1], KH[2*jj+1][0], KH[2*jj+1][1],
                      sb + (uint32_t)(jj * 16 * FPB) + boff + ks * 32);
            #pragma unroll
            for (int jj = 0; jj < 4; jj++)
                ldsm4(KL[2*jj][0], KL[2*jj][1], KL[2*jj+1][0], KL[2*jj+1][1],
                      sb + FPLANE + (uint32_t)(jj * 16 * FPB) + boff + ks * 32);
            #pragma unroll
            for (int nt = 0; nt < 8; nt++) {
                mma16816(sacc[nt], Qh4[ks], KH[nt]);
                mma16816(sacc[nt], Qh4[ks], KL[nt]);
                mma16816(sacc[nt], Ql4[ks], KH[nt]);
            }
        }

        // ---- online softmax in fragments ----
        float mx0 = -1e30f, mx1 = -1e30f;
        #pragma unroll
        for (int nt = 0; nt < 8; nt++) {
            int mk0 = mks[nt * 8 + cbase], mk1 = mks[nt * 8 + cbase + 1];
            float s0 = mk0 ? sacc[nt][0] * SCL : -1e30f;
            float s1 = mk1 ? sacc[nt][1] * SCL : -1e30f;
            float s2 = mk0 ? sacc[nt][2] * SCL : -1e30f;
            float s3 = mk1 ? sacc[nt][3] * SCL : -1e30f;
            sacc[nt][0] = s0; sacc[nt][1] = s1; sacc[nt][2] = s2; sacc[nt][3] = s3;
            mx0 = fmaxf(mx0, fmaxf(s0, s1));
            mx1 = fmaxf(mx1, fmaxf(s2, s3));
        }
        mx0 = fmaxf(mx0, __shfl_xor_sync(0xffffffffu, mx0, 1));
        mx0 = fmaxf(mx0, __shfl_xor_sync(0xffffffffu, mx0, 2));
        mx1 = fmaxf(mx1, __shfl_xor_sync(0xffffffffu, mx1, 1));
        mx1 = fmaxf(mx1, __shfl_xor_sync(0xffffffffu, mx1, 2));

        const float mn0 = fmaxf(m0, mx0), mn1 = fmaxf(m1, mx1);
        const float a0 = __expf(m0 - mn0), a1 = __expf(m1 - mn1);

        float rs0 = 0.0f, rs1 = 0.0f;
        uint32_t Ph[4][4], Pl[4][4];
        #pragma unroll
        for (int ks = 0; ks < 4; ks++) {
            #pragma unroll
            for (int half = 0; half < 2; half++) {
                const int nt = 2 * ks + half;
                float p0 = __expf(sacc[nt][0] - mn0);
                float p1 = __expf(sacc[nt][1] - mn0);
                float p2 = __expf(sacc[nt][2] - mn1);
                float p3 = __expf(sacc[nt][3] - mn1);
                rs0 += p0 + p1; rs1 += p2 + p3;
                float h0 = __bfloat162float(__float2bfloat16(p0));
                float h1 = __bfloat162float(__float2bfloat16(p1));
                float h2 = __bfloat162float(__float2bfloat16(p2));
                float h3 = __bfloat162float(__float2bfloat16(p3));
                Ph[ks][2*half + 0] = pack_bf16(h0, h1);
                Ph[ks][2*half + 1] = pack_bf16(h2, h3);
                Pl[ks][2*half + 0] = pack_bf16(p0 - h0, p1 - h1);
                Pl[ks][2*half + 1] = pack_bf16(p2 - h2, p3 - h3);
            }
        }
        rs0 += __shfl_xor_sync(0xffffffffu, rs0, 1);
        rs0 += __shfl_xor_sync(0xffffffffu, rs0, 2);
        rs1 += __shfl_xor_sync(0xffffffffu, rs1, 1);
        rs1 += __shfl_xor_sync(0xffffffffu, rs1, 2);

        l0 = l0 * a0 + rs0;
        l1 = l1 * a1 + rs1;
        m0 = mn0; m1 = mn1;
        #pragma unroll
        for (int nt = 0; nt < 8; nt++) {
            oacc[nt][0] *= a0; oacc[nt][1] *= a0;
            oacc[nt][2] *= a1; oacc[nt][3] *= a1;
        }

        // ---- O += P V (split) ----
        #pragma unroll
        for (int ks = 0; ks < 4; ks++) {
            uint32_t VH[8][2], VL[8][2];
            #pragma unroll
            for (int g = 0; g < 4; g++)
                ldsm4t(VH[2*g][0], VH[2*g][1], VH[2*g+1][0], VH[2*g+1][1],
                       sb + 2 * FPLANE + (uint32_t)(ks * 16 * FPB) + g * 32 + voff);
            #pragma unroll
            for (int g = 0; g < 4; g++)
                ldsm4t(VL[2*g][0], VL[2*g][1], VL[2*g+1][0], VL[2*g+1][1],
                       sb + 3 * FPLANE + (uint32_t)(ks * 16 * FPB) + g * 32 + voff);
            #pragma unroll
            for (int nt = 0; nt < 8; nt++) {
                mma16816(oacc[nt], Ph[ks], VH[nt]);
                mma16816(oacc[nt], Ph[ks], VL[nt]);
                mma16816(oacc[nt], Pl[ks], VH[nt]);
            }
        }
        __syncthreads();
    }

    // ---- finalize: out = oacc / l, split to hi/lo planes ----
    const float inv0 = 1.0f / l0, inv1 = 1.0f / l1;
    const int row0g = b * SS + q0 + 16 * wrp + (lane >> 2);
    const int row1g = row0g + 8;
    #pragma unroll
    for (int nt = 0; nt < 8; nt++) {
        const int col = h * DK + nt * 8 + cbase;
        float o0 = oacc[nt][0] * inv0, o1 = oacc[nt][1] * inv0;
        float o2 = oacc[nt][2] * inv1, o3 = oacc[nt][3] * inv1;
        float h0 = __bfloat162float(__float2bfloat16(o0));
        float h1 = __bfloat162float(__float2bfloat16(o1));
        float h2 = __bfloat162float(__float2bfloat16(o2));
        float h3 = __bfloat162float(__float2bfloat16(o3));
        *(uint32_t*)(oh + (size_t)row0g * DD + col) = pack_bf16(h0, h1);
        *(uint32_t*)(oh + (size_t)row1g * DD + col) = pack_bf16(h2, h3);
        *(uint32_t*)(ol + (size_t)row0g * DD + col) = pack_bf16(o0 - h0, o1 - h1);
        *(uint32_t*)(ol + (size_t)row1g * DD + col) = pack_bf16(o2 - h2, o3 - h3);
    }
}

// ============================================================================
// kernel_launch
// ============================================================================
extern "C" void kernel_launch(void* const* d_in, const int* in_sizes, int n_in,
                              void* d_out, int out_size)
{
    const float* x    = (const float*)d_in[0];
    const int*   mask = (const int*)  d_in[1];
    const float* wq   = (const float*)d_in[2];
    const float* bq   = (const float*)d_in[3];
    const float* wk   = (const float*)d_in[4];
    const float* bk   = (const float*)d_in[5];
    const float* wv   = (const float*)d_in[6];
    const float* bv   = (const float*)d_in[7];
    const float* wo   = (const float*)d_in[8];
    const float* bo   = (const float*)d_in[9];
    const float* w1   = (const float*)d_in[10];
    const float* b1   = (const float*)d_in[11];
    const float* w2   = (const float*)d_in[12];
    const float* b2   = (const float*)d_in[13];
    const float* ln1w = (const float*)d_in[14];
    const float* ln1b = (const float*)d_in[15];
    const float* ln2w = (const float*)d_in[16];
    const float* ln2b = (const float*)d_in[17];
    float* out = (float*)d_out;

    __nv_bfloat16 *xnh, *xnl, *ath, *atl, *ffh, *ffl;
    __nv_bfloat16 *qh, *ql, *kh, *kl, *vh, *vl;
    __nv_bfloat16 *wqh, *wql, *wkh, *wkl, *wvh, *wvl, *woh, *wol, *w1h, *w1l, *w2h, *w2l;
    cudaGetSymbolAddress((void**)&xnh, g_xnh);  cudaGetSymbolAddress((void**)&xnl, g_xnl);
    cudaGetSymbolAddress((void**)&qh,  g_qh);   cudaGetSymbolAddress((void**)&ql,  g_ql);
    cudaGetSymbolAddress((void**)&kh,  g_kh);   cudaGetSymbolAddress((void**)&kl,  g_kl);
    cudaGetSymbolAddress((void**)&vh,  g_vh);   cudaGetSymbolAddress((void**)&vl,  g_vl);
    cudaGetSymbolAddress((void**)&ath, g_ath);  cudaGetSymbolAddress((void**)&atl, g_atl);
    cudaGetSymbolAddress((void**)&ffh, g_ffh);  cudaGetSymbolAddress((void**)&ffl, g_ffl);
    cudaGetSymbolAddress((void**)&wqh, g_wqh);  cudaGetSymbolAddress((void**)&wql, g_wql);
    cudaGetSymbolAddress((void**)&wkh, g_wkh);  cudaGetSymbolAddress((void**)&wkl, g_wkl);
    cudaGetSymbolAddress((void**)&wvh, g_wvh);  cudaGetSymbolAddress((void**)&wvl, g_wvl);
    cudaGetSymbolAddress((void**)&woh, g_woh);  cudaGetSymbolAddress((void**)&wol, g_wol);
    cudaGetSymbolAddress((void**)&w1h, g_w1h);  cudaGetSymbolAddress((void**)&w1l, g_w1l);
    cudaGetSymbolAddress((void**)&w2h, g_w2h);  cudaGetSymbolAddress((void**)&w2l, g_w2l);

    cudaFuncSetAttribute(flash_mma,
                         cudaFuncAttributeMaxDynamicSharedMemorySize, FSMEM);
    cudaFuncSetAttribute(mma_gemm<0>,
                         cudaFuncAttributeMaxDynamicSharedMemorySize, GSMEM);
    cudaFuncSetAttribute(mma_gemm<1>,
                         cudaFuncAttributeMaxDynamicSharedMemorySize, GSMEM);
    cudaFuncSetAttribute(mma_gemm<2>,
                         cudaFuncAttributeMaxDynamicSharedMemorySize, GSMEM);
    cudaFuncSetAttribute(mma_gemm<3>,
                         cudaFuncAttributeMaxDynamicSharedMemorySize, GSMEM);

    dim3 tb(32, 8);
    // weight transpose + split  (W[K,N] -> T[N,K] hi/lo)
    wsplit_kernel<<<dim3(DD/32,  DD/32),  tb>>>(wq, wqh, wql, DD, DD);
    wsplit_kernel<<<dim3(DD/32,  DD/32),  tb>>>(wk, wkh, wkl, DD, DD);
    wsplit_kernel<<<dim3(DD/32,  DD/32),  tb>>>(wv, wvh, wvl, DD, DD);
    wsplit_kernel<<<dim3(DD/32,  DD/32),  tb>>>(wo, woh, wol, DD, DD);
    wsplit_kernel<<<dim3(DFF/32, DD/32),  tb>>>(w1, w1h, w1l, DD, DFF);
    wsplit_kernel<<<dim3(DD/32,  DFF/32), tb>>>(w2, w2h, w2l, DFF, DD);

    // 1. ln1 -> hi/lo planes
    ln_split_kernel<<<MM, 256>>>(x, ln1w, ln1b, xnh, xnl);

    // 2-4. Q, K, V projections -> bf16 hi/lo planes
    dim3 g1(DD / 128, MM / 128);
    mma_gemm<3><<<g1, 256, GSMEM>>>(xnh, xnl, wqh, wql, bq, nullptr, nullptr, qh, ql, DD, DD);
    mma_gemm<3><<<g1, 256, GSMEM>>>(xnh, xnl, wkh, wkl, bk, nullptr, nullptr, kh, kl, DD, DD);
    mma_gemm<3><<<g1, 256, GSMEM>>>(xnh, xnl, wvh, wvl, bv, nullptr, nullptr, vh, vl, DD, DD);

    // 5. attention (tensor-core flash) -> hi/lo planes
    dim3 gf(SS / 128, HH, BB);
    flash_mma<<<gf, 256, FSMEM>>>(qh, ql, kh, kl, vh, vl, mask, ath, atl);

    // 6. O projection + residual -> h1 (fp32) in d_out
    mma_gemm<2><<<g1, 256, GSMEM>>>(ath, atl, woh, wol, bo, x, out, nullptr, nullptr, DD, DD);

    // 7. ln2 -> hi/lo planes
    ln_split_kernel<<<MM, 256>>>(out, ln2w, ln2b, xnh, xnl);

    // 8. FFN up + relu  (N=4096) -> hi/lo planes
    dim3 g2(DFF / 128, MM / 128);
    mma_gemm<1><<<g2, 256, GSMEM>>>(xnh, xnl, w1h, w1l, b1, nullptr, nullptr, ffh, ffl, DFF, DD);

    // 9. FFN down + residual  (K=4096), fp32 out (in-place on d_out)
    mma_gemm<2><<<g1, 256, GSMEM>>>(ffh, ffl, w2h, w2l, b2, out, out, nullptr, nullptr, DD, DFF);
}

// round 14
// speedup vs baseline: 6.2331x; 2.4132x over previous
#include <cuda_runtime.h>
#include <cuda_fp16.h>
#include <math.h>
#include <stdint.h>

// Problem constants
constexpr int BB  = 4;
constexpr int SS  = 2048;
constexpr int DD  = 1024;
constexpr int HH  = 16;
constexpr int DK  = 64;
constexpr int DFF = 4096;
constexpr int MM  = BB * SS;           // 8192 rows

// ---------------- scratch (device globals; allocation is forbidden) --------
__device__ __half g_xn [(size_t)MM * DD];
__device__ __half g_qv [(size_t)MM * DD];
__device__ __half g_kv [(size_t)MM * DD];
__device__ __half g_vv [(size_t)MM * DD];
__device__ __half g_at [(size_t)MM * DD];
__device__ __half g_ff [(size_t)MM * DFF];
// transposed weights: [N,K] K-major fp16
__device__ __half g_wq[DD*DD], g_wk[DD*DD], g_wv[DD*DD], g_wo[DD*DD];
__device__ __half g_w1[(size_t)DD*DFF], g_w2[(size_t)DD*DFF];

// ============================================================================
// PTX helpers (family-safe: ldmatrix / mma.sync / cp.async only)
// ============================================================================
__device__ __forceinline__ uint32_t smem_u32(const void* p) {
    uint32_t a;
    asm("{ .reg .u64 t; cvta.to.shared.u64 t, %1; cvt.u32.u64 %0, t; }"
        : "=r"(a) : "l"(p));
    return a;
}
__device__ __forceinline__ void ldsm4(uint32_t& r0, uint32_t& r1,
                                      uint32_t& r2, uint32_t& r3, uint32_t addr) {
    asm volatile("ldmatrix.sync.aligned.m8n8.x4.shared.b16 {%0,%1,%2,%3}, [%4];"
                 : "=r"(r0), "=r"(r1), "=r"(r2), "=r"(r3) : "r"(addr));
}
__device__ __forceinline__ void ldsm4t(uint32_t& r0, uint32_t& r1,
                                       uint32_t& r2, uint32_t& r3, uint32_t addr) {
    asm volatile("ldmatrix.sync.aligned.m8n8.x4.trans.shared.b16 {%0,%1,%2,%3}, [%4];"
                 : "=r"(r0), "=r"(r1), "=r"(r2), "=r"(r3) : "r"(addr));
}
__device__ __forceinline__ void mma16816(float* c, const uint32_t* a, const uint32_t* b) {
    asm volatile(
        "mma.sync.aligned.m16n8k16.row.col.f32.f16.f16.f32 "
        "{%0,%1,%2,%3}, {%4,%5,%6,%7}, {%8,%9}, {%0,%1,%2,%3};"
        : "+f"(c[0]), "+f"(c[1]), "+f"(c[2]), "+f"(c[3])
        : "r"(a[0]), "r"(a[1]), "r"(a[2]), "r"(a[3]), "r"(b[0]), "r"(b[1]));
}
__device__ __forceinline__ void cp16(uint32_t dst, const void* src) {
    asm volatile("cp.async.cg.shared.global [%0], [%1], 16;" :: "r"(dst), "l"(src));
}
__device__ __forceinline__ void cp_commit() {
    asm volatile("cp.async.commit_group;" ::: "memory");
}
template<int N>
__device__ __forceinline__ void cp_wait() {
    asm volatile("cp.async.wait_group %0;" :: "n"(N) : "memory");
}
__device__ __forceinline__ uint32_t pack_h2(float a, float b) {
    __half2 t = __floats2half2_rn(a, b);   // .x = a (low), .y = b (high)
    return *(uint32_t*)&t;
}

// ============================================================================
// Weight transpose + fp16 convert:  W[K,N] f32  ->  T[N,K] fp16
// ============================================================================
__global__ __launch_bounds__(256) void whalf_kernel(
    const float* __restrict__ W, __half* __restrict__ T, int K, int N)
{
    __shared__ float t[32][33];
    const int tx = threadIdx.x, ty = threadIdx.y;
    const int n0 = blockIdx.x * 32, k0 = blockIdx.y * 32;
    #pragma unroll
    for (int i = 0; i < 32; i += 8)
        t[ty + i][tx] = W[(size_t)(k0 + ty + i) * N + n0 + tx];
    __syncthreads();
    #pragma unroll
    for (int i = 0; i < 32; i += 8)
        T[(size_t)(n0 + ty + i) * K + k0 + tx] = __float2half_rn(t[tx][ty + i]);
}

// ============================================================================
// LayerNorm (ddof=1, denom = std + eps), fp16 output
// ============================================================================
__global__ __launch_bounds__(256) void ln_half_kernel(
    const float* __restrict__ x, const float* __restrict__ w,
    const float* __restrict__ b, __half* __restrict__ o)
{
    const int row = blockIdx.x;
    const int tid = threadIdx.x;
    float4 v = ((const float4*)(x + (size_t)row * DD))[tid];

    float s  = v.x + v.y + v.z + v.w;
    float s2 = v.x*v.x + v.y*v.y + v.z*v.z + v.w*v.w;
    #pragma unroll
    for (int off = 16; off; off >>= 1) {
        s  += __shfl_xor_sync(0xffffffffu, s,  off);
        s2 += __shfl_xor_sync(0xffffffffu, s2, off);
    }
    __shared__ float rs[8], rs2[8];
    if ((tid & 31) == 0) { rs[tid >> 5] = s; rs2[tid >> 5] = s2; }
    __syncthreads();
    float ts = 0.f, ts2 = 0.f;
    #pragma unroll
    for (int i = 0; i < 8; i++) { ts += rs[i]; ts2 += rs2[i]; }

    const float mean = ts * (1.0f / (float)DD);
    float var = (ts2 - (float)DD * mean * mean) * (1.0f / (float)(DD - 1));
    var = fmaxf(var, 0.0f);
    const float inv = 1.0f / (sqrtf(var) + 1e-6f);

    float4 wv = ((const float4*)w)[tid];
    float4 bv = ((const float4*)b)[tid];
    uint2 u;
    u.x = pack_h2(wv.x * (v.x - mean) * inv + bv.x,
                  wv.y * (v.y - mean) * inv + bv.y);
    u.y = pack_h2(wv.z * (v.z - mean) * inv + bv.z,
                  wv.w * (v.w - mean) * inv + bv.w);
    *(uint2*)(o + (size_t)row * DD + tid * 4) = u;
}

// ============================================================================
// fp16 GEMM on mma.sync (HMMA).  C[M,N] = epi(A @ B^T + bias)
//   A: [M,K] fp16;  B: [N,K] fp16 (K-major)
//   Block 128x128, BK=32, 8 warps (2x4), warp tile 64x32, fp32 accum.
//   EPI: 0 = bias -> f32; 1 = bias+relu -> fp16; 2 = bias+resid -> f32
//        3 = bias -> fp16
// ============================================================================
constexpr int PITCH  = 40;                 // fp16 per smem row (32 + 8 pad)
constexpr int PITCHB = PITCH * 2;          // 80 bytes
constexpr int PLANE  = 128 * PITCHB;       // 10240 B
constexpr int STAGE  = 2 * PLANE;          // 20480 B (A + B)
constexpr int GSMEM  = 2 * STAGE;          // 40960 B

template<int EPI>
__global__ __launch_bounds__(256, 2) void mma_gemm(
    const __half* __restrict__ A, const __half* __restrict__ B,
    const float* __restrict__ bias, const float* __restrict__ resid,
    float* __restrict__ Cf, __half* __restrict__ Ch,
    int N, int K)
{
    extern __shared__ char sm[];
    const uint32_t base = smem_u32(sm);

    const int tid  = threadIdx.x;
    const int lane = tid & 31;
    const int wid  = tid >> 5;
    const int wr   = wid >> 2;      // 0..1 (64 rows each)
    const int wc   = wid & 3;       // 0..3 (32 cols each)
    const int row0 = blockIdx.y * 128;
    const int col0 = blockIdx.x * 128;

    const __half* gA[2] = { A + (size_t)row0 * K, B + (size_t)col0 * K };

    auto prefetch = [&](int st, int c) {
        const int k0 = c * 32;
        const uint32_t sb = base + st * STAGE;
        #pragma unroll
        for (int p = 0; p < 2; p++) {
            #pragma unroll
            for (int it = 0; it < 2; it++) {
                int idx = it * 256 + tid;
                int r = idx >> 2, ch = idx & 3;
                cp16(sb + p * PLANE + r * PITCHB + ch * 16,
                     gA[p] + (size_t)r * K + k0 + ch * 8);
            }
        }
        cp_commit();
    };

    float acc[4][4][4];
    #pragma unroll
    for (int i = 0; i < 4; i++)
        #pragma unroll
        for (int j = 0; j < 4; j++)
            #pragma unroll
            for (int e = 0; e < 4; e++) acc[i][j][e] = 0.0f;

    const int NC = K >> 5;
    prefetch(0, 0);

    const uint32_t a_off = (uint32_t)((wr * 64 + (lane & 15)) * PITCHB + (lane >> 4) * 16);
    const uint32_t b_off = (uint32_t)((wc * 32 + (lane & 7) + ((lane >> 4) & 1) * 8) * PITCHB
                                      + ((lane >> 3) & 1) * 16);

    for (int c = 0; c < NC; c++) {
        if (c + 1 < NC) { prefetch((c + 1) & 1, c + 1); cp_wait<1>(); }
        else            { cp_wait<0>(); }
        __syncthreads();

        const uint32_t aS = base + (c & 1) * STAGE;
        const uint32_t bS = aS + PLANE;

        #pragma unroll
        for (int ks = 0; ks < 2; ks++) {
            const uint32_t kb = ks * 32;
            uint32_t Af[4][4], Bf[4][2];
            #pragma unroll
            for (int i = 0; i < 4; i++)
                ldsm4(Af[i][0], Af[i][1], Af[i][2], Af[i][3],
                      aS + a_off + (uint32_t)(i * 16 * PITCHB) + kb);
            #pragma unroll
            for (int jj = 0; jj < 2; jj++)
                ldsm4(Bf[2*jj][0], Bf[2*jj][1], Bf[2*jj+1][0], Bf[2*jj+1][1],
                      bS + b_off + (uint32_t)(jj * 16 * PITCHB) + kb);
            #pragma unroll
            for (int i = 0; i < 4; i++)
                #pragma unroll
                for (int j = 0; j < 4; j++)
                    mma16816(acc[i][j], Af[i], Bf[j]);
        }
        __syncthreads();
    }

    // epilogue: direct stores from fragments
    #pragma unroll
    for (int i = 0; i < 4; i++) {
        const int m0 = row0 + wr * 64 + i * 16 + (lane >> 2);
        #pragma unroll
        for (int j = 0; j < 4; j++) {
            const int nb = col0 + wc * 32 + j * 8 + (lane & 3) * 2;
            const float2 bv = *(const float2*)(bias + nb);
            float c0 = acc[i][j][0] + bv.x, c1 = acc[i][j][1] + bv.y;
            float c2 = acc[i][j][2] + bv.x, c3 = acc[i][j][3] + bv.y;
            const size_t o0 = (size_t)m0 * N + nb;
            const size_t o1 = (size_t)(m0 + 8) * N + nb;
            if (EPI == 2) {
                float2 r0 = *(const float2*)(resid + o0);
                float2 r1 = *(const float2*)(resid + o1);
                c0 += r0.x; c1 += r0.y; c2 += r1.x; c3 += r1.y;
            }
            if (EPI == 1 || EPI == 3) {
                if (EPI == 1) {
                    c0 = fmaxf(c0, 0.f); c1 = fmaxf(c1, 0.f);
                    c2 = fmaxf(c2, 0.f); c3 = fmaxf(c3, 0.f);
                }
                *(uint32_t*)(Ch + o0) = pack_h2(c0, c1);
                *(uint32_t*)(Ch + o1) = pack_h2(c2, c3);
            } else {
                *(float2*)(Cf + o0) = make_float2(c0, c1);
                *(float2*)(Cf + o1) = make_float2(c2, c3);
            }
        }
    }
}

// ============================================================================
// Flash attention on mma.sync fp16, online softmax in fragments.
// Block = 128 queries x one (b,h). 8 warps x 16 query rows. Key tiles of 64.
// smem: K/V tiles, pitch 144B (72 fp16) -> conflict-free ldmatrix (+trans).
// ============================================================================
constexpr int FPB    = 144;            // bytes per 64-dk row in smem
constexpr int FPLANE = 64 * FPB;       // 9216 B (64 keys)
constexpr int FSTAGE = 2 * FPLANE;     // K,V = 18432 B
constexpr int FMSK   = 2 * FSTAGE;     // mask area offset (36864)
constexpr int FSMEM  = 2 * FSTAGE + 512;
constexpr float SCL  = 0.125f;         // 1/sqrt(64)

__global__ __launch_bounds__(256, 1) void flash_mma(
    const __half* __restrict__ q, const __half* __restrict__ k,
    const __half* __restrict__ v, const int* __restrict__ mask,
    __half* __restrict__ oat)
{
    extern __shared__ char sm[];
    const uint32_t base = smem_u32(sm);

    const int tid  = threadIdx.x;
    const int lane = tid & 31;
    const int wrp  = tid >> 5;
    const int b = blockIdx.z, h = blockIdx.y;
    const int q0 = blockIdx.x * 128;

    const size_t bh_off = (size_t)(b * SS) * DD + h * DK;
    const __half* gp[2] = { k + bh_off, v + bh_off };
    const int* mask_p = mask + (size_t)b * SS;

    // ---- load Q tile (128 rows x 64 dk) via stage0 area ----
    {
        const __half* qp = q + bh_off + (size_t)q0 * DD;
        #pragma unroll
        for (int it = 0; it < 4; it++) {
            int rem = it * 256 + tid;
            int row = rem >> 3, ch = rem & 7;
            cp16(base + row * FPB + ch * 16, qp + (size_t)row * DD + ch * 8);
        }
        cp_commit();
        cp_wait<0>();
        __syncthreads();
    }

    uint32_t Qf[4][4];
    {
        const uint32_t qoff = (uint32_t)((16 * wrp + (lane & 15)) * FPB + (lane >> 4) * 16);
        #pragma unroll
        for (int ks = 0; ks < 4; ks++)
            ldsm4(Qf[ks][0], Qf[ks][1], Qf[ks][2], Qf[ks][3], base + qoff + ks * 32);
    }
    __syncthreads();   // done with Q staging area before K/V prefetch reuses it

    auto prefetch = [&](int st, int t) {
        const int key0 = t * 64;
        const uint32_t sb = base + st * FSTAGE;
        #pragma unroll
        for (int p = 0; p < 2; p++) {
            #pragma unroll
            for (int half = 0; half < 2; half++) {
                int rem = half * 256 + tid;
                int row = rem >> 3, ch = rem & 7;
                cp16(sb + p * FPLANE + row * FPB + ch * 16,
                     gp[p] + (size_t)(key0 + row) * DD + ch * 8);
            }
        }
        if (tid < 16)
            cp16(base + FMSK + st * 256 + tid * 16, mask_p + key0 + tid * 4);
        cp_commit();
    };

    float oacc[8][4];
    #pragma unroll
    for (int nt = 0; nt < 8; nt++)
        #pragma unroll
        for (int e = 0; e < 4; e++) oacc[nt][e] = 0.0f;
    float m0 = -1e30f, m1 = -1e30f, l0 = 0.0f, l1 = 0.0f;

    const uint32_t boff = (uint32_t)(((lane & 7) + ((lane >> 4) & 1) * 8) * FPB
                                     + ((lane >> 3) & 1) * 16);
    const uint32_t voff = (uint32_t)(((lane & 7) + ((lane >> 3) & 1) * 8) * FPB
                                     + ((lane >> 4) & 1) * 16);
    const int cbase = (lane & 3) * 2;

    constexpr int NT = SS / 64;   // 32 key tiles
    prefetch(0, 0);

    for (int c = 0; c < NT; c++) {
        if (c + 1 < NT) { prefetch((c + 1) & 1, c + 1); cp_wait<1>(); }
        else            { cp_wait<0>(); }
        __syncthreads();

        const uint32_t sb = base + (c & 1) * FSTAGE;
        const int* mks = (const int*)(sm + FMSK + (c & 1) * 256);

        // ---- S = Q K^T ----
        float sacc[8][4];
        #pragma unroll
        for (int nt = 0; nt < 8; nt++)
            #pragma unroll
            for (int e = 0; e < 4; e++) sacc[nt][e] = 0.0f;

        #pragma unroll
        for (int ks = 0; ks < 4; ks++) {
            uint32_t KF[8][2];
            #pragma unroll
            for (int jj = 0; jj < 4; jj++)
                ldsm4(KF[2*jj][0], KF[2*jj][1], KF[2*jj+1][0], KF[2*jj+1][1],
                      sb + (uint32_t)(jj * 16 * FPB) + boff + ks * 32);
            #pragma unroll
            for (int nt = 0; nt < 8; nt++)
                mma16816(sacc[nt], Qf[ks], KF[nt]);
        }

        // ---- online softmax in fragments ----
        float mx0 = -1e30f, mx1 = -1e30f;
        #pragma unroll
        for (int nt = 0; nt < 8; nt++) {
            int mk0 = mks[nt * 8 + cbase], mk1 = mks[nt * 8 + cbase + 1];
            float s0 = mk0 ? sacc[nt][0] * SCL : -1e30f;
            float s1 = mk1 ? sacc[nt][1] * SCL : -1e30f;
            float s2 = mk0 ? sacc[nt][2] * SCL : -1e30f;
            float s3 = mk1 ? sacc[nt][3] * SCL : -1e30f;
            sacc[nt][0] = s0; sacc[nt][1] = s1; sacc[nt][2] = s2; sacc[nt][3] = s3;
            mx0 = fmaxf(mx0, fmaxf(s0, s1));
            mx1 = fmaxf(mx1, fmaxf(s2, s3));
        }
        mx0 = fmaxf(mx0, __shfl_xor_sync(0xffffffffu, mx0, 1));
        mx0 = fmaxf(mx0, __shfl_xor_sync(0xffffffffu, mx0, 2));
        mx1 = fmaxf(mx1, __shfl_xor_sync(0xffffffffu, mx1, 1));
        mx1 = fmaxf(mx1, __shfl_xor_sync(0xffffffffu, mx1, 2));

        const float mn0 = fmaxf(m0, mx0), mn1 = fmaxf(m1, mx1);
        const float a0 = __expf(m0 - mn0), a1 = __expf(m1 - mn1);

        float rs0 = 0.0f, rs1 = 0.0f;
        uint32_t Pf[4][4];
        #pragma unroll
        for (int ks = 0; ks < 4; ks++) {
            #pragma unroll
            for (int half = 0; half < 2; half++) {
                const int nt = 2 * ks + half;
                float p0 = __expf(sacc[nt][0] - mn0);
                float p1 = __expf(sacc[nt][1] - mn0);
                float p2 = __expf(sacc[nt][2] - mn1);
                float p3 = __expf(sacc[nt][3] - mn1);
                rs0 += p0 + p1; rs1 += p2 + p3;
                Pf[ks][2*half + 0] = pack_h2(p0, p1);
                Pf[ks][2*half + 1] = pack_h2(p2, p3);
            }
        }
        rs0 += __shfl_xor_sync(0xffffffffu, rs0, 1);
        rs0 += __shfl_xor_sync(0xffffffffu, rs0, 2);
        rs1 += __shfl_xor_sync(0xffffffffu, rs1, 1);
        rs1 += __shfl_xor_sync(0xffffffffu, rs1, 2);

        l0 = l0 * a0 + rs0;
        l1 = l1 * a1 + rs1;
        m0 = mn0; m1 = mn1;
        #pragma unroll
        for (int nt = 0; nt < 8; nt++) {
            oacc[nt][0] *= a0; oacc[nt][1] *= a0;
            oacc[nt][2] *= a1; oacc[nt][3] *= a1;
        }

        // ---- O += P V ----
        #pragma unroll
        for (int ks = 0; ks < 4; ks++) {
            uint32_t VF[8][2];
            #pragma unroll
            for (int g = 0; g < 4; g++)
                ldsm4t(VF[2*g][0], VF[2*g][1], VF[2*g+1][0], VF[2*g+1][1],
                       sb + FPLANE + (uint32_t)(ks * 16 * FPB) + g * 32 + voff);
            #pragma unroll
            for (int nt = 0; nt < 8; nt++)
                mma16816(oacc[nt], Pf[ks], VF[nt]);
        }
        __syncthreads();
    }

    // ---- finalize: out = oacc / l -> fp16 ----
    const float inv0 = 1.0f / l0, inv1 = 1.0f / l1;
    const int row0g = b * SS + q0 + 16 * wrp + (lane >> 2);
    const int row1g = row0g + 8;
    #pragma unroll
    for (int nt = 0; nt < 8; nt++) {
        const int col = h * DK + nt * 8 + cbase;
        *(uint32_t*)(oat + (size_t)row0g * DD + col) =
            pack_h2(oacc[nt][0] * inv0, oacc[nt][1] * inv0);
        *(uint32_t*)(oat + (size_t)row1g * DD + col) =
            pack_h2(oacc[nt][2] * inv1, oacc[nt][3] * inv1);
    }
}

// ============================================================================
// kernel_launch
// ============================================================================
extern "C" void kernel_launch(void* const* d_in, const int* in_sizes, int n_in,
                              void* d_out, int out_size)
{
    const float* x    = (const float*)d_in[0];
    const int*   mask = (const int*)  d_in[1];
    const float* wq   = (const float*)d_in[2];
    const float* bq   = (const float*)d_in[3];
    const float* wk   = (const float*)d_in[4];
    const float* bk   = (const float*)d_in[5];
    const float* wv   = (const float*)d_in[6];
    const float* bv   = (const float*)d_in[7];
    const float* wo   = (const float*)d_in[8];
    const float* bo   = (const float*)d_in[9];
    const float* w1   = (const float*)d_in[10];
    const float* b1   = (const float*)d_in[11];
    const float* w2   = (const float*)d_in[12];
    const float* b2   = (const float*)d_in[13];
    const float* ln1w = (const float*)d_in[14];
    const float* ln1b = (const float*)d_in[15];
    const float* ln2w = (const float*)d_in[16];
    const float* ln2b = (const float*)d_in[17];
    float* out = (float*)d_out;

    __half *xn, *qv, *kv, *vv, *at, *ff;
    __half *twq, *twk, *twv, *two, *tw1, *tw2;
    cudaGetSymbolAddress((void**)&xn,  g_xn);
    cudaGetSymbolAddress((void**)&qv,  g_qv);
    cudaGetSymbolAddress((void**)&kv,  g_kv);
    cudaGetSymbolAddress((void**)&vv,  g_vv);
    cudaGetSymbolAddress((void**)&at,  g_at);
    cudaGetSymbolAddress((void**)&ff,  g_ff);
    cudaGetSymbolAddress((void**)&twq, g_wq);
    cudaGetSymbolAddress((void**)&twk, g_wk);
    cudaGetSymbolAddress((void**)&twv, g_wv);
    cudaGetSymbolAddress((void**)&two, g_wo);
    cudaGetSymbolAddress((void**)&tw1, g_w1);
    cudaGetSymbolAddress((void**)&tw2, g_w2);

    cudaFuncSetAttribute(flash_mma,
                         cudaFuncAttributeMaxDynamicSharedMemorySize, FSMEM);
    cudaFuncSetAttribute(mma_gemm<0>,
                         cudaFuncAttributeMaxDynamicSharedMemorySize, GSMEM);
    cudaFuncSetAttribute(mma_gemm<1>,
                         cudaFuncAttributeMaxDynamicSharedMemorySize, GSMEM);
    cudaFuncSetAttribute(mma_gemm<2>,
                         cudaFuncAttributeMaxDynamicSharedMemorySize, GSMEM);
    cudaFuncSetAttribute(mma_gemm<3>,
                         cudaFuncAttributeMaxDynamicSharedMemorySize, GSMEM);

    dim3 tb(32, 8);
    // weight transpose + fp16 convert  (W[K,N] -> T[N,K])
    whalf_kernel<<<dim3(DD/32,  DD/32),  tb>>>(wq, twq, DD, DD);
    whalf_kernel<<<dim3(DD/32,  DD/32),  tb>>>(wk, twk, DD, DD);
    whalf_kernel<<<dim3(DD/32,  DD/32),  tb>>>(wv, twv, DD, DD);
    whalf_kernel<<<dim3(DD/32,  DD/32),  tb>>>(wo, two, DD, DD);
    whalf_kernel<<<dim3(DFF/32, DD/32),  tb>>>(w1, tw1, DD, DFF);
    whalf_kernel<<<dim3(DD/32,  DFF/32), tb>>>(w2, tw2, DFF, DD);

    // 1. ln1 -> fp16
    ln_half_kernel<<<MM, 256>>>(x, ln1w, ln1b, xn);

    // 2-4. Q, K, V projections -> fp16
    dim3 g1(DD / 128, MM / 128);
    mma_gemm<3><<<g1, 256, GSMEM>>>(xn, twq, bq, nullptr, nullptr, qv, DD, DD);
    mma_gemm<3><<<g1, 256, GSMEM>>>(xn, twk, bk, nullptr, nullptr, kv, DD, DD);
    mma_gemm<3><<<g1, 256, GSMEM>>>(xn, twv, bv, nullptr, nullptr, vv, DD, DD);

    // 5. attention (tensor-core flash) -> fp16
    dim3 gf(SS / 128, HH, BB);
    flash_mma<<<gf, 256, FSMEM>>>(qv, kv, vv, mask, at);

    // 6. O projection + residual -> h1 (fp32) in d_out
    mma_gemm<2><<<g1, 256, GSMEM>>>(at, two, bo, x, out, nullptr, DD, DD);

    // 7. ln2 -> fp16
    ln_half_kernel<<<MM, 256>>>(out, ln2w, ln2b, xn);

    // 8. FFN up + relu  (N=4096) -> fp16
    dim3 g2(DFF / 128, MM / 128);
    mma_gemm<1><<<g2, 256, GSMEM>>>(xn, tw1, b1, nullptr, nullptr, ff, DFF, DD);

    // 9. FFN down + residual  (K=4096), fp32 out (in-place on d_out)
    mma_gemm<2><<<g1, 256, GSMEM>>>(ff, tw2, b2, out, out, nullptr, DD, DFF);
}

// round 16
// speedup vs baseline: 7.0444x; 1.1302x over previous
#include <cuda_runtime.h>
#include <cuda_fp16.h>
#include <math.h>
#include <stdint.h>

// Problem constants
constexpr int BB  = 4;
constexpr int SS  = 2048;
constexpr int DD  = 1024;
constexpr int HH  = 16;
constexpr int DK  = 64;
constexpr int DFF = 4096;
constexpr int MM  = BB * SS;           // 8192 rows
constexpr int QN  = 3 * DD;            // fused qkv width (3072)

// ---------------- scratch (device globals; allocation is forbidden) --------
__device__ __half g_xn  [(size_t)MM * DD];
__device__ __half g_qkv [(size_t)MM * QN];
__device__ __half g_at  [(size_t)MM * DD];
__device__ __half g_ff  [(size_t)MM * DFF];
// transposed weights: [N,K] K-major fp16
__device__ __half g_wqkv[(size_t)QN * DD];       // rows 0-1023 q, 1024-2047 k, 2048-3071 v
__device__ __half g_wo[DD*DD];
__device__ __half g_w1[(size_t)DD*DFF], g_w2[(size_t)DD*DFF];
__device__ float  g_bqkv[QN];

// ============================================================================
// PTX helpers (family-safe: ldmatrix / mma.sync / cp.async only)
// ============================================================================
__device__ __forceinline__ uint32_t smem_u32(const void* p) {
    uint32_t a;
    asm("{ .reg .u64 t; cvta.to.shared.u64 t, %1; cvt.u32.u64 %0, t; }"
        : "=r"(a) : "l"(p));
    return a;
}
__device__ __forceinline__ void ldsm4(uint32_t& r0, uint32_t& r1,
                                      uint32_t& r2, uint32_t& r3, uint32_t addr) {
    asm volatile("ldmatrix.sync.aligned.m8n8.x4.shared.b16 {%0,%1,%2,%3}, [%4];"
                 : "=r"(r0), "=r"(r1), "=r"(r2), "=r"(r3) : "r"(addr));
}
__device__ __forceinline__ void ldsm4t(uint32_t& r0, uint32_t& r1,
                                       uint32_t& r2, uint32_t& r3, uint32_t addr) {
    asm volatile("ldmatrix.sync.aligned.m8n8.x4.trans.shared.b16 {%0,%1,%2,%3}, [%4];"
                 : "=r"(r0), "=r"(r1), "=r"(r2), "=r"(r3) : "r"(addr));
}
__device__ __forceinline__ void mma16816(float* c, const uint32_t* a, const uint32_t* b) {
    asm volatile(
        "mma.sync.aligned.m16n8k16.row.col.f32.f16.f16.f32 "
        "{%0,%1,%2,%3}, {%4,%5,%6,%7}, {%8,%9}, {%0,%1,%2,%3};"
        : "+f"(c[0]), "+f"(c[1]), "+f"(c[2]), "+f"(c[3])
        : "r"(a[0]), "r"(a[1]), "r"(a[2]), "r"(a[3]), "r"(b[0]), "r"(b[1]));
}
__device__ __forceinline__ void cp16(uint32_t dst, const void* src) {
    asm volatile("cp.async.cg.shared.global [%0], [%1], 16;" :: "r"(dst), "l"(src));
}
__device__ __forceinline__ void cp_commit() {
    asm volatile("cp.async.commit_group;" ::: "memory");
}
template<int N>
__device__ __forceinline__ void cp_wait() {
    asm volatile("cp.async.wait_group %0;" :: "n"(N) : "memory");
}
__device__ __forceinline__ uint32_t pack_h2(float a, float b) {
    __half2 t = __floats2half2_rn(a, b);   // .x = a (low), .y = b (high)
    return *(uint32_t*)&t;
}

// ============================================================================
// Weight transpose + fp16 convert:  W[K,N] f32  ->  T[N,K] fp16
// ============================================================================
__global__ __launch_bounds__(256) void whalf_kernel(
    const float* __restrict__ W, __half* __restrict__ T, int K, int N)
{
    __shared__ float t[32][33];
    const int tx = threadIdx.x, ty = threadIdx.y;
    const int n0 = blockIdx.x * 32, k0 = blockIdx.y * 32;
    #pragma unroll
    for (int i = 0; i < 32; i += 8)
        t[ty + i][tx] = W[(size_t)(k0 + ty + i) * N + n0 + tx];
    __syncthreads();
    #pragma unroll
    for (int i = 0; i < 32; i += 8)
        T[(size_t)(n0 + ty + i) * K + k0 + tx] = __float2half_rn(t[tx][ty + i]);
}

// ============================================================================
// LayerNorm (ddof=1, denom = std + eps), fp16 output
// ============================================================================
__global__ __launch_bounds__(256) void ln_half_kernel(
    const float* __restrict__ x, const float* __restrict__ w,
    const float* __restrict__ b, __half* __restrict__ o)
{
    const int row = blockIdx.x;
    const int tid = threadIdx.x;
    float4 v = ((const float4*)(x + (size_t)row * DD))[tid];

    float s  = v.x + v.y + v.z + v.w;
    float s2 = v.x*v.x + v.y*v.y + v.z*v.z + v.w*v.w;
    #pragma unroll
    for (int off = 16; off; off >>= 1) {
        s  += __shfl_xor_sync(0xffffffffu, s,  off);
        s2 += __shfl_xor_sync(0xffffffffu, s2, off);
    }
    __shared__ float rs[8], rs2[8];
    if ((tid & 31) == 0) { rs[tid >> 5] = s; rs2[tid >> 5] = s2; }
    __syncthreads();
    float ts = 0.f, ts2 = 0.f;
    #pragma unroll
    for (int i = 0; i < 8; i++) { ts += rs[i]; ts2 += rs2[i]; }

    const float mean = ts * (1.0f / (float)DD);
    float var = (ts2 - (float)DD * mean * mean) * (1.0f / (float)(DD - 1));
    var = fmaxf(var, 0.0f);
    const float inv = 1.0f / (sqrtf(var) + 1e-6f);

    float4 wv = ((const float4*)w)[tid];
    float4 bv = ((const float4*)b)[tid];
    uint2 u;
    u.x = pack_h2(wv.x * (v.x - mean) * inv + bv.x,
                  wv.y * (v.y - mean) * inv + bv.y);
    u.y = pack_h2(wv.z * (v.z - mean) * inv + bv.z,
                  wv.w * (v.w - mean) * inv + bv.w);
    *(uint2*)(o + (size_t)row * DD + tid * 4) = u;
}

// ============================================================================
// fp16 GEMM on mma.sync (HMMA).  C[M,N] = epi(A @ B^T + bias)
//   A: [M,K] fp16;  B: [N,K] fp16 (K-major)
//   Block 128x128, BK=32, 8 warps (2x4), warp tile 64x32, fp32 accum.
//   3-stage cp.async pipeline, one __syncthreads per K-iteration.
//   EPI: 1 = bias+relu -> fp16; 2 = bias+resid -> f32; 3 = bias -> fp16
// ============================================================================
constexpr int PITCH  = 40;                 // fp16 per smem row (32 + 8 pad)
constexpr int PITCHB = PITCH * 2;          // 80 bytes
constexpr int PLANE  = 128 * PITCHB;       // 10240 B
constexpr int STAGE  = 2 * PLANE;          // 20480 B (A + B)
constexpr int GSMEM  = 3 * STAGE;          // 61440 B (3 stages)

template<int EPI>
__global__ __launch_bounds__(256, 2) void mma_gemm(
    const __half* __restrict__ A, const __half* __restrict__ B,
    const float* __restrict__ bias, const float* __restrict__ resid,
    float* __restrict__ Cf, __half* __restrict__ Ch,
    int N, int K)
{
    extern __shared__ char sm[];
    const uint32_t base = smem_u32(sm);

    const int tid  = threadIdx.x;
    const int lane = tid & 31;
    const int wid  = tid >> 5;
    const int wr   = wid >> 2;      // 0..1 (64 rows each)
    const int wc   = wid & 3;       // 0..3 (32 cols each)
    const int row0 = blockIdx.y * 128;
    const int col0 = blockIdx.x * 128;

    const __half* gA[2] = { A + (size_t)row0 * K, B + (size_t)col0 * K };

    auto prefetch = [&](int st, int c) {
        const int k0 = c * 32;
        const uint32_t sb = base + st * STAGE;
        #pragma unroll
        for (int p = 0; p < 2; p++) {
            #pragma unroll
            for (int it = 0; it < 2; it++) {
                int idx = it * 256 + tid;
                int r = idx >> 2, ch = idx & 3;
                cp16(sb + p * PLANE + r * PITCHB + ch * 16,
                     gA[p] + (size_t)r * K + k0 + ch * 8);
            }
        }
        cp_commit();
    };

    float acc[4][4][4];
    #pragma unroll
    for (int i = 0; i < 4; i++)
        #pragma unroll
        for (int j = 0; j < 4; j++)
            #pragma unroll
            for (int e = 0; e < 4; e++) acc[i][j][e] = 0.0f;

    const int NC = K >> 5;
    prefetch(0, 0);
    prefetch(1, 1);

    const uint32_t a_off = (uint32_t)((wr * 64 + (lane & 15)) * PITCHB + (lane >> 4) * 16);
    const uint32_t b_off = (uint32_t)((wc * 32 + (lane & 7) + ((lane >> 4) & 1) * 8) * PITCHB
                                      + ((lane >> 3) & 1) * 16);

    for (int c = 0; c < NC; c++) {
        if (c < NC - 1) cp_wait<1>();
        else            cp_wait<0>();
        __syncthreads();

        if (c + 2 < NC) prefetch((c + 2) % 3, c + 2);

        const uint32_t aS = base + (c % 3) * STAGE;
        const uint32_t bS = aS + PLANE;

        #pragma unroll
        for (int ks = 0; ks < 2; ks++) {
            const uint32_t kb = ks * 32;
            uint32_t Af[4][4], Bf[4][2];
            #pragma unroll
            for (int i = 0; i < 4; i++)
                ldsm4(Af[i][0], Af[i][1], Af[i][2], Af[i][3],
                      aS + a_off + (uint32_t)(i * 16 * PITCHB) + kb);
            #pragma unroll
            for (int jj = 0; jj < 2; jj++)
                ldsm4(Bf[2*jj][0], Bf[2*jj][1], Bf[2*jj+1][0], Bf[2*jj+1][1],
                      bS + b_off + (uint32_t)(jj * 16 * PITCHB) + kb);
            #pragma unroll
            for (int i = 0; i < 4; i++)
                #pragma unroll
                for (int j = 0; j < 4; j++)
                    mma16816(acc[i][j], Af[i], Bf[j]);
        }
    }
    __syncthreads();

    // epilogue: direct stores from fragments
    #pragma unroll
    for (int i = 0; i < 4; i++) {
        const int m0 = row0 + wr * 64 + i * 16 + (lane >> 2);
        #pragma unroll
        for (int j = 0; j < 4; j++) {
            const int nb = col0 + wc * 32 + j * 8 + (lane & 3) * 2;
            const float2 bv = *(const float2*)(bias + nb);
            float c0 = acc[i][j][0] + bv.x, c1 = acc[i][j][1] + bv.y;
            float c2 = acc[i][j][2] + bv.x, c3 = acc[i][j][3] + bv.y;
            const size_t o0 = (size_t)m0 * N + nb;
            const size_t o1 = (size_t)(m0 + 8) * N + nb;
            if (EPI == 2) {
                float2 r0 = *(const float2*)(resid + o0);
                float2 r1 = *(const float2*)(resid + o1);
                c0 += r0.x; c1 += r0.y; c2 += r1.x; c3 += r1.y;
            }
            if (EPI == 1 || EPI == 3) {
                if (EPI == 1) {
                    c0 = fmaxf(c0, 0.f); c1 = fmaxf(c1, 0.f);
                    c2 = fmaxf(c2, 0.f); c3 = fmaxf(c3, 0.f);
                }
                *(uint32_t*)(Ch + o0) = pack_h2(c0, c1);
                *(uint32_t*)(Ch + o1) = pack_h2(c2, c3);
            } else {
                *(float2*)(Cf + o0) = make_float2(c0, c1);
                *(float2*)(Cf + o1) = make_float2(c2, c3);
            }
        }
    }
}

// ============================================================================
// Flash attention on mma.sync fp16, online softmax in fragments.
// Block = 128 queries x one (b,h). 8 warps x 16 query rows. Key tiles of 128.
// Q/K/V come from the fused qkv buffer [M, 3072] (q|k|v sections).
// smem: K/V tiles, pitch 144B (72 fp16) -> conflict-free ldmatrix (+trans).
// ============================================================================
constexpr int KT     = 128;            // keys per tile
constexpr int FPB    = 144;            // bytes per 64-dk row in smem
constexpr int FPLANE = KT * FPB;       // 18432 B
constexpr int FSTAGE = 2 * FPLANE;     // K,V = 36864 B
constexpr int FMSK   = 2 * FSTAGE;     // mask area offset (73728)
constexpr int FSMEM  = FMSK + 2 * 512; // 74752 B
constexpr float SCL2 = 0.125f * 1.44269504f;   // (1/sqrt(64)) * log2(e)

__global__ __launch_bounds__(256, 1) void flash_mma(
    const __half* __restrict__ qkv, const int* __restrict__ mask,
    __half* __restrict__ oat)
{
    extern __shared__ char sm[];
    const uint32_t base = smem_u32(sm);

    const int tid  = threadIdx.x;
    const int lane = tid & 31;
    const int wrp  = tid >> 5;
    const int b = blockIdx.z, h = blockIdx.y;
    const int q0 = blockIdx.x * 128;

    const size_t rowb = (size_t)(b * SS);
    const __half* qp = qkv + (rowb + q0) * QN + h * DK;
    const __half* gp[2] = { qkv + rowb * QN + DD     + h * DK,      // K
                            qkv + rowb * QN + 2 * DD + h * DK };    // V
    const int* mask_p = mask + (size_t)b * SS;

    // ---- load Q tile (128 rows x 64 dk) via stage0 area ----
    {
        #pragma unroll
        for (int it = 0; it < 4; it++) {
            int rem = it * 256 + tid;
            int row = rem >> 3, ch = rem & 7;
            cp16(base + row * FPB + ch * 16, qp + (size_t)row * QN + ch * 8);
        }
        cp_commit();
        cp_wait<0>();
        __syncthreads();
    }

    uint32_t Qf[4][4];
    {
        const uint32_t qoff = (uint32_t)((16 * wrp + (lane & 15)) * FPB + (lane >> 4) * 16);
        #pragma unroll
        for (int ks = 0; ks < 4; ks++)
            ldsm4(Qf[ks][0], Qf[ks][1], Qf[ks][2], Qf[ks][3], base + qoff + ks * 32);
    }
    __syncthreads();   // done with Q staging area before K/V prefetch reuses it

    auto prefetch = [&](int st, int t) {
        const int key0 = t * KT;
        const uint32_t sb = base + st * FSTAGE;
        #pragma unroll
        for (int p = 0; p < 2; p++) {
            #pragma unroll
            for (int it = 0; it < 4; it++) {
                int rem = it * 256 + tid;
                int row = rem >> 3, ch = rem & 7;
                cp16(sb + p * FPLANE + row * FPB + ch * 16,
                     gp[p] + (size_t)(key0 + row) * QN + ch * 8);
            }
        }
        if (tid < 32)
            cp16(base + FMSK + st * 512 + tid * 16, mask_p + key0 + tid * 4);
        cp_commit();
    };

    float oacc[8][4];
    #pragma unroll
    for (int nt = 0; nt < 8; nt++)
        #pragma unroll
        for (int e = 0; e < 4; e++) oacc[nt][e] = 0.0f;
    float m0 = -1e30f, m1 = -1e30f, l0 = 0.0f, l1 = 0.0f;

    const uint32_t boff = (uint32_t)(((lane & 7) + ((lane >> 4) & 1) * 8) * FPB
                                     + ((lane >> 3) & 1) * 16);
    const uint32_t voff = (uint32_t)(((lane & 7) + ((lane >> 3) & 1) * 8) * FPB
                                     + ((lane >> 4) & 1) * 16);
    const int cbase = (lane & 3) * 2;

    constexpr int NT = SS / KT;   // 16 key tiles
    prefetch(0, 0);

    for (int c = 0; c < NT; c++) {
        if (c + 1 < NT) { prefetch((c + 1) & 1, c + 1); cp_wait<1>(); }
        else            { cp_wait<0>(); }
        __syncthreads();

        const uint32_t sb = base + (c & 1) * FSTAGE;
        const int* mks = (const int*)(sm + FMSK + (c & 1) * 512);

        // ---- S = Q K^T  (16 n-tiles of 8 keys) ----
        float sacc[16][4];
        #pragma unroll
        for (int nt = 0; nt < 16; nt++)
            #pragma unroll
            for (int e = 0; e < 4; e++) sacc[nt][e] = 0.0f;

        #pragma unroll
        for (int ks = 0; ks < 4; ks++) {
            uint32_t KF[16][2];
            #pragma unroll
            for (int jj = 0; jj < 8; jj++)
                ldsm4(KF[2*jj][0], KF[2*jj][1], KF[2*jj+1][0], KF[2*jj+1][1],
                      sb + (uint32_t)(jj * 16 * FPB) + boff + ks * 32);
            #pragma unroll
            for (int nt = 0; nt < 16; nt++)
                mma16816(sacc[nt], Qf[ks], KF[nt]);
        }

        // ---- online softmax in fragments (log2 domain) ----
        float mx0 = -1e30f, mx1 = -1e30f;
        #pragma unroll
        for (int nt = 0; nt < 16; nt++) {
            int mk0 = mks[nt * 8 + cbase], mk1 = mks[nt * 8 + cbase + 1];
            float s0 = mk0 ? sacc[nt][0] * SCL2 : -1e30f;
            float s1 = mk1 ? sacc[nt][1] * SCL2 : -1e30f;
            float s2 = mk0 ? sacc[nt][2] * SCL2 : -1e30f;
            float s3 = mk1 ? sacc[nt][3] * SCL2 : -1e30f;
            sacc[nt][0] = s0; sacc[nt][1] = s1; sacc[nt][2] = s2; sacc[nt][3] = s3;
            mx0 = fmaxf(mx0, fmaxf(s0, s1));
            mx1 = fmaxf(mx1, fmaxf(s2, s3));
        }
        mx0 = fmaxf(mx0, __shfl_xor_sync(0xffffffffu, mx0, 1));
        mx0 = fmaxf(mx0, __shfl_xor_sync(0xffffffffu, mx0, 2));
        mx1 = fmaxf(mx1, __shfl_xor_sync(0xffffffffu, mx1, 1));
        mx1 = fmaxf(mx1, __shfl_xor_sync(0xffffffffu, mx1, 2));

        const float mn0 = fmaxf(m0, mx0), mn1 = fmaxf(m1, mx1);
        const float a0 = exp2f(m0 - mn0), a1 = exp2f(m1 - mn1);

        float rs0 = 0.0f, rs1 = 0.0f;
        uint32_t Pf[8][4];
        #pragma unroll
        for (int ks = 0; ks < 8; ks++) {
            #pragma unroll
            for (int half = 0; half < 2; half++) {
                const int nt = 2 * ks + half;
                float p0 = exp2f(sacc[nt][0] - mn0);
                float p1 = exp2f(sacc[nt][1] - mn0);
                float p2 = exp2f(sacc[nt][2] - mn1);
                float p3 = exp2f(sacc[nt][3] - mn1);
                rs0 += p0 + p1; rs1 += p2 + p3;
                Pf[ks][2*half + 0] = pack_h2(p0, p1);
                Pf[ks][2*half + 1] = pack_h2(p2, p3);
            }
        }
        rs0 += __shfl_xor_sync(0xffffffffu, rs0, 1);
        rs0 += __shfl_xor_sync(0xffffffffu, rs0, 2);
        rs1 += __shfl_xor_sync(0xffffffffu, rs1, 1);
        rs1 += __shfl_xor_sync(0xffffffffu, rs1, 2);

        l0 = l0 * a0 + rs0;
        l1 = l1 * a1 + rs1;
        m0 = mn0; m1 = mn1;
        #pragma unroll
        for (int nt = 0; nt < 8; nt++) {
            oacc[nt][0] *= a0; oacc[nt][1] *= a0;
            oacc[nt][2] *= a1; oacc[nt][3] *= a1;
        }

        // ---- O += P V ----
        #pragma unroll
        for (int ks = 0; ks < 8; ks++) {
            uint32_t VF[8][2];
            #pragma unroll
            for (int g = 0; g < 4; g++)
                ldsm4t(VF[2*g][0], VF[2*g][1], VF[2*g+1][0], VF[2*g+1][1],
                       sb + FPLANE + (uint32_t)(ks * 16 * FPB) + g * 32 + voff);
            #pragma unroll
            for (int nt = 0; nt < 8; nt++)
                mma16816(oacc[nt], Pf[ks], VF[nt]);
        }
        __syncthreads();
    }

    // ---- finalize: out = oacc / l -> fp16 ----
    const float inv0 = 1.0f / l0, inv1 = 1.0f / l1;
    const int row0g = b * SS + q0 + 16 * wrp + (lane >> 2);
    const int row1g = row0g + 8;
    #pragma unroll
    for (int nt = 0; nt < 8; nt++) {
        const int col = h * DK + nt * 8 + cbase;
        *(uint32_t*)(oat + (size_t)row0g * DD + col) =
            pack_h2(oacc[nt][0] * inv0, oacc[nt][1] * inv0);
        *(uint32_t*)(oat + (size_t)row1g * DD + col) =
            pack_h2(oacc[nt][2] * inv1, oacc[nt][3] * inv1);
    }
}

// ============================================================================
// kernel_launch
// ============================================================================
extern "C" void kernel_launch(void* const* d_in, const int* in_sizes, int n_in,
                              void* d_out, int out_size)
{
    const float* x    = (const float*)d_in[0];
    const int*   mask = (const int*)  d_in[1];
    const float* wq   = (const float*)d_in[2];
    const float* bq   = (const float*)d_in[3];
    const float* wk   = (const float*)d_in[4];
    const float* bk   = (const float*)d_in[5];
    const float* wv   = (const float*)d_in[6];
    const float* bv   = (const float*)d_in[7];
    const float* wo   = (const float*)d_in[8];
    const float* bo   = (const float*)d_in[9];
    const float* w1   = (const float*)d_in[10];
    const float* b1   = (const float*)d_in[11];
    const float* w2   = (const float*)d_in[12];
    const float* b2   = (const float*)d_in[13];
    const float* ln1w = (const float*)d_in[14];
    const float* ln1b = (const float*)d_in[15];
    const float* ln2w = (const float*)d_in[16];
    const float* ln2b = (const float*)d_in[17];
    float* out = (float*)d_out;

    __half *xn, *qkv, *at, *ff;
    __half *twqkv, *two, *tw1, *tw2;
    float  *bqkv;
    cudaGetSymbolAddress((void**)&xn,    g_xn);
    cudaGetSymbolAddress((void**)&qkv,   g_qkv);
    cudaGetSymbolAddress((void**)&at,    g_at);
    cudaGetSymbolAddress((void**)&ff,    g_ff);
    cudaGetSymbolAddress((void**)&twqkv, g_wqkv);
    cudaGetSymbolAddress((void**)&two,   g_wo);
    cudaGetSymbolAddress((void**)&tw1,   g_w1);
    cudaGetSymbolAddress((void**)&tw2,   g_w2);
    cudaGetSymbolAddress((void**)&bqkv,  g_bqkv);

    cudaFuncSetAttribute(flash_mma,
                         cudaFuncAttributeMaxDynamicSharedMemorySize, FSMEM);
    cudaFuncSetAttribute(mma_gemm<1>,
                         cudaFuncAttributeMaxDynamicSharedMemorySize, GSMEM);
    cudaFuncSetAttribute(mma_gemm<2>,
                         cudaFuncAttributeMaxDynamicSharedMemorySize, GSMEM);
    cudaFuncSetAttribute(mma_gemm<3>,
                         cudaFuncAttributeMaxDynamicSharedMemorySize, GSMEM);

    dim3 tb(32, 8);
    // weight transpose + fp16 convert (W[K,N] -> T[N,K]); q|k|v sections fused
    whalf_kernel<<<dim3(DD/32,  DD/32),  tb>>>(wq, twqkv,             DD, DD);
    whalf_kernel<<<dim3(DD/32,  DD/32),  tb>>>(wk, twqkv + DD*DD,     DD, DD);
    whalf_kernel<<<dim3(DD/32,  DD/32),  tb>>>(wv, twqkv + 2*DD*DD,   DD, DD);
    whalf_kernel<<<dim3(DD/32,  DD/32),  tb>>>(wo, two, DD, DD);
    whalf_kernel<<<dim3(DFF/32, DD/32),  tb>>>(w1, tw1, DD, DFF);
    whalf_kernel<<<dim3(DD/32,  DFF/32), tb>>>(w2, tw2, DFF, DD);
    // fused qkv bias
    cudaMemcpyAsync(bqkv,          bq, DD * sizeof(float), cudaMemcpyDeviceToDevice);
    cudaMemcpyAsync(bqkv + DD,     bk, DD * sizeof(float), cudaMemcpyDeviceToDevice);
    cudaMemcpyAsync(bqkv + 2*DD,   bv, DD * sizeof(float), cudaMemcpyDeviceToDevice);

    // 1. ln1 -> fp16
    ln_half_kernel<<<MM, 256>>>(x, ln1w, ln1b, xn);

    // 2. fused QKV projection (N=3072) -> fp16 qkv buffer
    dim3 gqkv(QN / 128, MM / 128);
    mma_gemm<3><<<gqkv, 256, GSMEM>>>(xn, twqkv, bqkv, nullptr, nullptr, qkv, QN, DD);

    // 3. attention (tensor-core flash) -> fp16
    dim3 gf(SS / 128, HH, BB);
    flash_mma<<<gf, 256, FSMEM>>>(qkv, mask, at);

    // 4. O projection + residual -> h1 (fp32) in d_out
    dim3 g1(DD / 128, MM / 128);
    mma_gemm<2><<<g1, 256, GSMEM>>>(at, two, bo, x, out, nullptr, DD, DD);

    // 5. ln2 -> fp16
    ln_half_kernel<<<MM, 256>>>(out, ln2w, ln2b, xn);

    // 6. FFN up + relu  (N=4096) -> fp16
    dim3 g2(DFF / 128, MM / 128);
    mma_gemm<1><<<g2, 256, GSMEM>>>(xn, tw1, b1, nullptr, nullptr, ff, DFF, DD);

    // 7. FFN down + residual  (K=4096), fp32 out (in-place on d_out)
    mma_gemm<2><<<g1, 256, GSMEM>>>(ff, tw2, b2, out, out, nullptr, DD, DFF);
}

// round 17
// speedup vs baseline: 7.1948x; 1.0214x over previous
#include <cuda_runtime.h>
#include <cuda_fp16.h>
#include <math.h>
#include <stdint.h>

// Problem constants
constexpr int BB  = 4;
constexpr int SS  = 2048;
constexpr int DD  = 1024;
constexpr int HH  = 16;
constexpr int DK  = 64;
constexpr int DFF = 4096;
constexpr int MM  = BB * SS;           // 8192 rows
constexpr int QN  = 3 * DD;            // fused qkv width (3072)

constexpr float SCL2 = 0.125f * 1.44269504f;   // (1/sqrt(64)) * log2(e)

// ---------------- scratch (device globals; allocation is forbidden) --------
__device__ __half g_xn  [(size_t)MM * DD];
__device__ __half g_qkv [(size_t)MM * QN];
__device__ __half g_at  [(size_t)MM * DD];
__device__ __half g_ff  [(size_t)MM * DFF];
// transposed weights: [N,K] K-major fp16
__device__ __half g_wqkv[(size_t)QN * DD];       // rows 0-1023 q, 1024-2047 k, 2048-3071 v
__device__ __half g_wo[DD*DD];
__device__ __half g_w1[(size_t)DD*DFF], g_w2[(size_t)DD*DFF];
__device__ float  g_bqkv[QN];

// ============================================================================
// PTX helpers (family-safe: ldmatrix / mma.sync / cp.async only)
// ============================================================================
__device__ __forceinline__ uint32_t smem_u32(const void* p) {
    uint32_t a;
    asm("{ .reg .u64 t; cvta.to.shared.u64 t, %1; cvt.u32.u64 %0, t; }"
        : "=r"(a) : "l"(p));
    return a;
}
__device__ __forceinline__ void ldsm4(uint32_t& r0, uint32_t& r1,
                                      uint32_t& r2, uint32_t& r3, uint32_t addr) {
    asm volatile("ldmatrix.sync.aligned.m8n8.x4.shared.b16 {%0,%1,%2,%3}, [%4];"
                 : "=r"(r0), "=r"(r1), "=r"(r2), "=r"(r3) : "r"(addr));
}
__device__ __forceinline__ void ldsm4t(uint32_t& r0, uint32_t& r1,
                                       uint32_t& r2, uint32_t& r3, uint32_t addr) {
    asm volatile("ldmatrix.sync.aligned.m8n8.x4.trans.shared.b16 {%0,%1,%2,%3}, [%4];"
                 : "=r"(r0), "=r"(r1), "=r"(r2), "=r"(r3) : "r"(addr));
}
__device__ __forceinline__ void mma16816(float* c, const uint32_t* a, const uint32_t* b) {
    asm volatile(
        "mma.sync.aligned.m16n8k16.row.col.f32.f16.f16.f32 "
        "{%0,%1,%2,%3}, {%4,%5,%6,%7}, {%8,%9}, {%0,%1,%2,%3};"
        : "+f"(c[0]), "+f"(c[1]), "+f"(c[2]), "+f"(c[3])
        : "r"(a[0]), "r"(a[1]), "r"(a[2]), "r"(a[3]), "r"(b[0]), "r"(b[1]));
}
__device__ __forceinline__ void cp16(uint32_t dst, const void* src) {
    asm volatile("cp.async.cg.shared.global [%0], [%1], 16;" :: "r"(dst), "l"(src));
}
__device__ __forceinline__ void cp_commit() {
    asm volatile("cp.async.commit_group;" ::: "memory");
}
template<int N>
__device__ __forceinline__ void cp_wait() {
    asm volatile("cp.async.wait_group %0;" :: "n"(N) : "memory");
}
__device__ __forceinline__ uint32_t pack_h2(float a, float b) {
    __half2 t = __floats2half2_rn(a, b);   // .x = a (low), .y = b (high)
    return *(uint32_t*)&t;
}
__device__ __forceinline__ uint32_t h2exp2(uint32_t x) {
    uint32_t r;
    asm volatile("ex2.approx.f16x2 %0, %1;" : "=r"(r) : "r"(x));
    return r;
}

// ============================================================================
// LayerNorm body (ddof=1, denom = std + eps), fp16 output. sh = 16 floats.
// ============================================================================
__device__ __forceinline__ void ln_body(
    const float* __restrict__ x, const float* __restrict__ w,
    const float* __restrict__ b, __half* __restrict__ o,
    int row, int tid, float* sh)
{
    float4 v = ((const float4*)(x + (size_t)row * DD))[tid];

    float s  = v.x + v.y + v.z + v.w;
    float s2 = v.x*v.x + v.y*v.y + v.z*v.z + v.w*v.w;
    #pragma unroll
    for (int off = 16; off; off >>= 1) {
        s  += __shfl_xor_sync(0xffffffffu, s,  off);
        s2 += __shfl_xor_sync(0xffffffffu, s2, off);
    }
    if ((tid & 31) == 0) { sh[tid >> 5] = s; sh[8 + (tid >> 5)] = s2; }
    __syncthreads();
    float ts = 0.f, ts2 = 0.f;
    #pragma unroll
    for (int i = 0; i < 8; i++) { ts += sh[i]; ts2 += sh[8 + i]; }

    const float mean = ts * (1.0f / (float)DD);
    float var = (ts2 - (float)DD * mean * mean) * (1.0f / (float)(DD - 1));
    var = fmaxf(var, 0.0f);
    const float inv = 1.0f / (sqrtf(var) + 1e-6f);

    float4 wv = ((const float4*)w)[tid];
    float4 bv = ((const float4*)b)[tid];
    uint2 u;
    u.x = pack_h2(wv.x * (v.x - mean) * inv + bv.x,
                  wv.y * (v.y - mean) * inv + bv.y);
    u.y = pack_h2(wv.z * (v.z - mean) * inv + bv.z,
                  wv.w * (v.w - mean) * inv + bv.w);
    *(uint2*)(o + (size_t)row * DD + tid * 4) = u;
}

__global__ __launch_bounds__(256) void ln_half_kernel(
    const float* __restrict__ x, const float* __restrict__ w,
    const float* __restrict__ b, __half* __restrict__ o)
{
    __shared__ float sh[16];
    ln_body(x, w, b, o, blockIdx.x, threadIdx.x, sh);
}

// ============================================================================
// Weight transpose body: W[K,N] f32 -> T[N,K] fp16, one 32x32 tile (flat 256)
// ============================================================================
__device__ __forceinline__ void wtrans_body(
    const float* __restrict__ W, __half* __restrict__ T,
    int K, int N, int l, int tid, float* t /* 32*33 floats */)
{
    const int tx = tid & 31, ty = tid >> 5;           // ty 0..7
    const int nb = N >> 5;
    const int n0 = (l % nb) * 32, k0 = (l / nb) * 32;
    #pragma unroll
    for (int i = 0; i < 32; i += 8)
        t[(ty + i) * 33 + tx] = W[(size_t)(k0 + ty + i) * N + n0 + tx];
    __syncthreads();
    #pragma unroll
    for (int i = 0; i < 32; i += 8)
        T[(size_t)(n0 + ty + i) * K + k0 + tx] = __float2half_rn(t[tx * 33 + ty + i]);
}

// ============================================================================
// Fused prep: ln1 + all 6 weight transposes + qkv bias concat, one launch.
// ============================================================================
constexpr int PB_LN = MM;                 // 8192 ln rows
constexpr int PB_T0 = PB_LN;              // wq   1024
constexpr int PB_T1 = PB_T0 + 1024;       // wk   1024
constexpr int PB_T2 = PB_T1 + 1024;       // wv   1024
constexpr int PB_T3 = PB_T2 + 1024;       // wo   1024
constexpr int PB_T4 = PB_T3 + 1024;       // w1   4096
constexpr int PB_T5 = PB_T4 + 4096;       // w2   4096
constexpr int PB_BI = PB_T5 + 4096;       // bias 12
constexpr int PB_TOT = PB_BI + 12;

__global__ __launch_bounds__(256) void prep_kernel(
    const float* __restrict__ x, const float* __restrict__ ln1w,
    const float* __restrict__ ln1b, __half* __restrict__ xn,
    const float* __restrict__ wq, const float* __restrict__ wk,
    const float* __restrict__ wv, const float* __restrict__ wo,
    const float* __restrict__ w1, const float* __restrict__ w2,
    __half* __restrict__ twqkv, __half* __restrict__ two,
    __half* __restrict__ tw1, __half* __restrict__ tw2,
    const float* __restrict__ bq, const float* __restrict__ bk,
    const float* __restrict__ bv, float* __restrict__ bqkv)
{
    __shared__ float sh[32 * 33];
    const int bid = blockIdx.x;
    const int tid = threadIdx.x;

    if (bid < PB_LN) {
        ln_body(x, ln1w, ln1b, xn, bid, tid, sh);
    } else if (bid < PB_T1) {
        wtrans_body(wq, twqkv,            DD, DD, bid - PB_T0, tid, sh);
    } else if (bid < PB_T2) {
        wtrans_body(wk, twqkv + DD*DD,    DD, DD, bid - PB_T1, tid, sh);
    } else if (bid < PB_T3) {
        wtrans_body(wv, twqkv + 2*DD*DD,  DD, DD, bid - PB_T2, tid, sh);
    } else if (bid < PB_T4) {
        wtrans_body(wo, two,              DD, DD, bid - PB_T3, tid, sh);
    } else if (bid < PB_T5) {
        wtrans_body(w1, tw1,              DD, DFF, bid - PB_T4, tid, sh);
    } else if (bid < PB_BI) {
        wtrans_body(w2, tw2,              DFF, DD, bid - PB_T5, tid, sh);
    } else {
        const int i = (bid - PB_BI) * 256 + tid;
        float v = (i < DD) ? bq[i] : (i < 2*DD) ? bk[i - DD] : bv[i - 2*DD];
        bqkv[i] = v;
    }
}

// ============================================================================
// fp16 GEMM on mma.sync (HMMA).  C[M,N] = epi(A @ B^T + bias)
//   Block 128x128, BK=32, 8 warps (2x4), warp tile 64x32, fp32 accum.
//   3-stage cp.async pipeline, one __syncthreads per K-iteration.
//   EPI: 1 = bias+relu -> fp16; 2 = bias+resid -> f32; 3 = bias -> fp16
//        4 = bias, then scale cols < DD by SCL2 -> fp16  (fused qkv)
// ============================================================================
constexpr int PITCH  = 40;                 // fp16 per smem row (32 + 8 pad)
constexpr int PITCHB = PITCH * 2;          // 80 bytes
constexpr int PLANE  = 128 * PITCHB;       // 10240 B
constexpr int STAGE  = 2 * PLANE;          // 20480 B (A + B)
constexpr int GSMEM  = 3 * STAGE;          // 61440 B (3 stages)

template<int EPI>
__global__ __launch_bounds__(256, 2) void mma_gemm(
    const __half* __restrict__ A, const __half* __restrict__ B,
    const float* __restrict__ bias, const float* __restrict__ resid,
    float* __restrict__ Cf, __half* __restrict__ Ch,
    int N, int K)
{
    extern __shared__ char sm[];
    const uint32_t base = smem_u32(sm);

    const int tid  = threadIdx.x;
    const int lane = tid & 31;
    const int wid  = tid >> 5;
    const int wr   = wid >> 2;      // 0..1 (64 rows each)
    const int wc   = wid & 3;       // 0..3 (32 cols each)
    const int row0 = blockIdx.y * 128;
    const int col0 = blockIdx.x * 128;

    const __half* gA[2] = { A + (size_t)row0 * K, B + (size_t)col0 * K };

    auto prefetch = [&](int st, int c) {
        const int k0 = c * 32;
        const uint32_t sb = base + st * STAGE;
        #pragma unroll
        for (int p = 0; p < 2; p++) {
            #pragma unroll
            for (int it = 0; it < 2; it++) {
                int idx = it * 256 + tid;
                int r = idx >> 2, ch = idx & 3;
                cp16(sb + p * PLANE + r * PITCHB + ch * 16,
                     gA[p] + (size_t)r * K + k0 + ch * 8);
            }
        }
        cp_commit();
    };

    float acc[4][4][4];
    #pragma unroll
    for (int i = 0; i < 4; i++)
        #pragma unroll
        for (int j = 0; j < 4; j++)
            #pragma unroll
            for (int e = 0; e < 4; e++) acc[i][j][e] = 0.0f;

    const int NC = K >> 5;
    prefetch(0, 0);
    prefetch(1, 1);

    const uint32_t a_off = (uint32_t)((wr * 64 + (lane & 15)) * PITCHB + (lane >> 4) * 16);
    const uint32_t b_off = (uint32_t)((wc * 32 + (lane & 7) + ((lane >> 4) & 1) * 8) * PITCHB
                                      + ((lane >> 3) & 1) * 16);

    for (int c = 0; c < NC; c++) {
        if (c < NC - 1) cp_wait<1>();
        else            cp_wait<0>();
        __syncthreads();

        if (c + 2 < NC) prefetch((c + 2) % 3, c + 2);

        const uint32_t aS = base + (c % 3) * STAGE;
        const uint32_t bS = aS + PLANE;

        #pragma unroll
        for (int ks = 0; ks < 2; ks++) {
            const uint32_t kb = ks * 32;
            uint32_t Af[4][4], Bf[4][2];
            #pragma unroll
            for (int i = 0; i < 4; i++)
                ldsm4(Af[i][0], Af[i][1], Af[i][2], Af[i][3],
                      aS + a_off + (uint32_t)(i * 16 * PITCHB) + kb);
            #pragma unroll
            for (int jj = 0; jj < 2; jj++)
                ldsm4(Bf[2*jj][0], Bf[2*jj][1], Bf[2*jj+1][0], Bf[2*jj+1][1],
                      bS + b_off + (uint32_t)(jj * 16 * PITCHB) + kb);
            #pragma unroll
            for (int i = 0; i < 4; i++)
                #pragma unroll
                for (int j = 0; j < 4; j++)
                    mma16816(acc[i][j], Af[i], Bf[j]);
        }
    }
    __syncthreads();

    // epilogue: direct stores from fragments
    #pragma unroll
    for (int i = 0; i < 4; i++) {
        const int m0 = row0 + wr * 64 + i * 16 + (lane >> 2);
        #pragma unroll
        for (int j = 0; j < 4; j++) {
            const int nb = col0 + wc * 32 + j * 8 + (lane & 3) * 2;
            const float2 bv = *(const float2*)(bias + nb);
            float c0 = acc[i][j][0] + bv.x, c1 = acc[i][j][1] + bv.y;
            float c2 = acc[i][j][2] + bv.x, c3 = acc[i][j][3] + bv.y;
            const size_t o0 = (size_t)m0 * N + nb;
            const size_t o1 = (size_t)(m0 + 8) * N + nb;
            if (EPI == 2) {
                float2 r0 = *(const float2*)(resid + o0);
                float2 r1 = *(const float2*)(resid + o1);
                c0 += r0.x; c1 += r0.y; c2 += r1.x; c3 += r1.y;
            }
            if (EPI == 1 || EPI == 3 || EPI == 4) {
                if (EPI == 1) {
                    c0 = fmaxf(c0, 0.f); c1 = fmaxf(c1, 0.f);
                    c2 = fmaxf(c2, 0.f); c3 = fmaxf(c3, 0.f);
                }
                if (EPI == 4) {
                    const float scl = (nb < DD) ? SCL2 : 1.0f;
                    c0 *= scl; c1 *= scl; c2 *= scl; c3 *= scl;
                }
                *(uint32_t*)(Ch + o0) = pack_h2(c0, c1);
                *(uint32_t*)(Ch + o1) = pack_h2(c2, c3);
            } else {
                *(float2*)(Cf + o0) = make_float2(c0, c1);
                *(float2*)(Cf + o1) = make_float2(c2, c3);
            }
        }
    }
}

// ============================================================================
// Flash attention on mma.sync fp16, online softmax in fragments.
// Block = 128 queries x one (b,h). 8 warps x 16 query rows. Key tiles of 128.
// Q comes pre-scaled by SCL2 (folded into qkv epilogue); scores are already
// in log2 domain. exp via ex2.approx.f16x2; row sums via ones-MMA.
// ============================================================================
constexpr int KT     = 128;            // keys per tile
constexpr int FPB    = 144;            // bytes per 64-dk row in smem
constexpr int FPLANE = KT * FPB;       // 18432 B
constexpr int FSTAGE = 2 * FPLANE;     // K,V = 36864 B
constexpr int FMSK   = 2 * FSTAGE;     // mask area offset (73728)
constexpr int FSMEM  = FMSK + 2 * 512; // 74752 B

__global__ __launch_bounds__(256, 1) void flash_mma(
    const __half* __restrict__ qkv, const int* __restrict__ mask,
    __half* __restrict__ oat)
{
    extern __shared__ char sm[];
    const uint32_t base = smem_u32(sm);

    const int tid  = threadIdx.x;
    const int lane = tid & 31;
    const int wrp  = tid >> 5;
    const int b = blockIdx.z, h = blockIdx.y;
    const int q0 = blockIdx.x * 128;

    const size_t rowb = (size_t)(b * SS);
    const __half* qp = qkv + (rowb + q0) * QN + h * DK;
    const __half* gp[2] = { qkv + rowb * QN + DD     + h * DK,      // K
                            qkv + rowb * QN + 2 * DD + h * DK };    // V
    const int* mask_p = mask + (size_t)b * SS;

    // ---- load Q tile (128 rows x 64 dk) via stage0 area ----
    {
        #pragma unroll
        for (int it = 0; it < 4; it++) {
            int rem = it * 256 + tid;
            int row = rem >> 3, ch = rem & 7;
            cp16(base + row * FPB + ch * 16, qp + (size_t)row * QN + ch * 8);
        }
        cp_commit();
        cp_wait<0>();
        __syncthreads();
    }

    uint32_t Qf[4][4];
    {
        const uint32_t qoff = (uint32_t)((16 * wrp + (lane & 15)) * FPB + (lane >> 4) * 16);
        #pragma unroll
        for (int ks = 0; ks < 4; ks++)
            ldsm4(Qf[ks][0], Qf[ks][1], Qf[ks][2], Qf[ks][3], base + qoff + ks * 32);
    }
    __syncthreads();   // done with Q staging area before K/V prefetch reuses it

    auto prefetch = [&](int st, int t) {
        const int key0 = t * KT;
        const uint32_t sb = base + st * FSTAGE;
        #pragma unroll
        for (int p = 0; p < 2; p++) {
            #pragma unroll
            for (int it = 0; it < 4; it++) {
                int rem = it * 256 + tid;
                int row = rem >> 3, ch = rem & 7;
                cp16(sb + p * FPLANE + row * FPB + ch * 16,
                     gp[p] + (size_t)(key0 + row) * QN + ch * 8);
            }
        }
        if (tid < 32)
            cp16(base + FMSK + st * 512 + tid * 16, mask_p + key0 + tid * 4);
        cp_commit();
    };

    float oacc[8][4];
    #pragma unroll
    for (int nt = 0; nt < 8; nt++)
        #pragma unroll
        for (int e = 0; e < 4; e++) oacc[nt][e] = 0.0f;
    float m0 = -1e30f, m1 = -1e30f, l0 = 0.0f, l1 = 0.0f;

    const uint32_t boff = (uint32_t)(((lane & 7) + ((lane >> 4) & 1) * 8) * FPB
                                     + ((lane >> 3) & 1) * 16);
    const uint32_t voff = (uint32_t)(((lane & 7) + ((lane >> 3) & 1) * 8) * FPB
                                     + ((lane >> 4) & 1) * 16);
    const int cbase = (lane & 3) * 2;
    const uint32_t ones_b[2] = { 0x3C003C00u, 0x3C003C00u };   // fp16 1.0 x4

    constexpr int NT = SS / KT;   // 16 key tiles
    prefetch(0, 0);

    for (int c = 0; c < NT; c++) {
        if (c + 1 < NT) { prefetch((c + 1) & 1, c + 1); cp_wait<1>(); }
        else            { cp_wait<0>(); }
        __syncthreads();

        const uint32_t sb = base + (c & 1) * FSTAGE;
        const int* mks = (const int*)(sm + FMSK + (c & 1) * 512);

        // ---- S = Q K^T  (16 n-tiles of 8 keys); Q pre-scaled: log2 domain ----
        float sacc[16][4];
        #pragma unroll
        for (int nt = 0; nt < 16; nt++)
            #pragma unroll
            for (int e = 0; e < 4; e++) sacc[nt][e] = 0.0f;

        #pragma unroll
        for (int ks = 0; ks < 4; ks++) {
            uint32_t KF[16][2];
            #pragma unroll
            for (int jj = 0; jj < 8; jj++)
                ldsm4(KF[2*jj][0], KF[2*jj][1], KF[2*jj+1][0], KF[2*jj+1][1],
                      sb + (uint32_t)(jj * 16 * FPB) + boff + ks * 32);
            #pragma unroll
            for (int nt = 0; nt < 16; nt++)
                mma16816(sacc[nt], Qf[ks], KF[nt]);
        }

        // ---- online softmax (log2 domain, fp16x2 exp) ----
        float mx0 = -1e30f, mx1 = -1e30f;
        #pragma unroll
        for (int nt = 0; nt < 16; nt++) {
            int mk0 = mks[nt * 8 + cbase], mk1 = mks[nt * 8 + cbase + 1];
            float s0 = mk0 ? sacc[nt][0] : -1e30f;
            float s1 = mk1 ? sacc[nt][1] : -1e30f;
            float s2 = mk0 ? sacc[nt][2] : -1e30f;
            float s3 = mk1 ? sacc[nt][3] : -1e30f;
            sacc[nt][0] = s0; sacc[nt][1] = s1; sacc[nt][2] = s2; sacc[nt][3] = s3;
            mx0 = fmaxf(mx0, fmaxf(s0, s1));
            mx1 = fmaxf(mx1, fmaxf(s2, s3));
        }
        mx0 = fmaxf(mx0, __shfl_xor_sync(0xffffffffu, mx0, 1));
        mx0 = fmaxf(mx0, __shfl_xor_sync(0xffffffffu, mx0, 2));
        mx1 = fmaxf(mx1, __shfl_xor_sync(0xffffffffu, mx1, 1));
        mx1 = fmaxf(mx1, __shfl_xor_sync(0xffffffffu, mx1, 2));

        const float mn0 = fmaxf(m0, mx0), mn1 = fmaxf(m1, mx1);
        const float a0 = exp2f(m0 - mn0), a1 = exp2f(m1 - mn1);

        uint32_t Pf[8][4];
        float lacc[4] = {0.f, 0.f, 0.f, 0.f};
        #pragma unroll
        for (int ks = 0; ks < 8; ks++) {
            #pragma unroll
            for (int half = 0; half < 2; half++) {
                const int nt = 2 * ks + half;
                Pf[ks][2*half + 0] = h2exp2(pack_h2(sacc[nt][0] - mn0,
                                                    sacc[nt][1] - mn0));
                Pf[ks][2*half + 1] = h2exp2(pack_h2(sacc[nt][2] - mn1,
                                                    sacc[nt][3] - mn1));
            }
        }
        // row sums via ones-MMA: lacc[0] = sum row r, lacc[2] = sum row r+8
        #pragma unroll
        for (int ks = 0; ks < 8; ks++)
            mma16816(lacc, Pf[ks], ones_b);

        l0 = l0 * a0 + lacc[0];
        l1 = l1 * a1 + lacc[2];
        m0 = mn0; m1 = mn1;
        #pragma unroll
        for (int nt = 0; nt < 8; nt++) {
            oacc[nt][0] *= a0; oacc[nt][1] *= a0;
            oacc[nt][2] *= a1; oacc[nt][3] *= a1;
        }

        // ---- O += P V ----
        #pragma unroll
        for (int ks = 0; ks < 8; ks++) {
            uint32_t VF[8][2];
            #pragma unroll
            for (int g = 0; g < 4; g++)
                ldsm4t(VF[2*g][0], VF[2*g][1], VF[2*g+1][0], VF[2*g+1][1],
                       sb + FPLANE + (uint32_t)(ks * 16 * FPB) + g * 32 + voff);
            #pragma unroll
            for (int nt = 0; nt < 8; nt++)
                mma16816(oacc[nt], Pf[ks], VF[nt]);
        }
        __syncthreads();
    }

    // ---- finalize: out = oacc / l -> fp16 ----
    const float inv0 = 1.0f / l0, inv1 = 1.0f / l1;
    const int row0g = b * SS + q0 + 16 * wrp + (lane >> 2);
    const int row1g = row0g + 8;
    #pragma unroll
    for (int nt = 0; nt < 8; nt++) {
        const int col = h * DK + nt * 8 + cbase;
        *(uint32_t*)(oat + (size_t)row0g * DD + col) =
            pack_h2(oacc[nt][0] * inv0, oacc[nt][1] * inv0);
        *(uint32_t*)(oat + (size_t)row1g * DD + col) =
            pack_h2(oacc[nt][2] * inv1, oacc[nt][3] * inv1);
    }
}

// ============================================================================
// kernel_launch
// ============================================================================
extern "C" void kernel_launch(void* const* d_in, const int* in_sizes, int n_in,
                              void* d_out, int out_size)
{
    const float* x    = (const float*)d_in[0];
    const int*   mask = (const int*)  d_in[1];
    const float* wq   = (const float*)d_in[2];
    const float* bq   = (const float*)d_in[3];
    const float* wk   = (const float*)d_in[4];
    const float* bk   = (const float*)d_in[5];
    const float* wv   = (const float*)d_in[6];
    const float* bv   = (const float*)d_in[7];
    const float* wo   = (const float*)d_in[8];
    const float* bo   = (const float*)d_in[9];
    const float* w1   = (const float*)d_in[10];
    const float* b1   = (const float*)d_in[11];
    const float* w2   = (const float*)d_in[12];
    const float* b2   = (const float*)d_in[13];
    const float* ln1w = (const float*)d_in[14];
    const float* ln1b = (const float*)d_in[15];
    const float* ln2w = (const float*)d_in[16];
    const float* ln2b = (const float*)d_in[17];
    float* out = (float*)d_out;

    __half *xn, *qkv, *at, *ff;
    __half *twqkv, *two, *tw1, *tw2;
    float  *bqkv;
    cudaGetSymbolAddress((void**)&xn,    g_xn);
    cudaGetSymbolAddress((void**)&qkv,   g_qkv);
    cudaGetSymbolAddress((void**)&at,    g_at);
    cudaGetSymbolAddress((void**)&ff,    g_ff);
    cudaGetSymbolAddress((void**)&twqkv, g_wqkv);
    cudaGetSymbolAddress((void**)&two,   g_wo);
    cudaGetSymbolAddress((void**)&tw1,   g_w1);
    cudaGetSymbolAddress((void**)&tw2,   g_w2);
    cudaGetSymbolAddress((void**)&bqkv,  g_bqkv);

    cudaFuncSetAttribute(flash_mma,
                         cudaFuncAttributeMaxDynamicSharedMemorySize, FSMEM);
    cudaFuncSetAttribute(mma_gemm<1>,
                         cudaFuncAttributeMaxDynamicSharedMemorySize, GSMEM);
    cudaFuncSetAttribute(mma_gemm<2>,
                         cudaFuncAttributeMaxDynamicSharedMemorySize, GSMEM);
    cudaFuncSetAttribute(mma_gemm<4>,
                         cudaFuncAttributeMaxDynamicSharedMemorySize, GSMEM);

    // 1. fused prep: ln1 + all weight transposes + qkv bias concat
    prep_kernel<<<PB_TOT, 256>>>(x, ln1w, ln1b, xn,
                                 wq, wk, wv, wo, w1, w2,
                                 twqkv, two, tw1, tw2,
                                 bq, bk, bv, bqkv);

    // 2. fused QKV projection (N=3072) -> fp16 qkv buffer (q cols pre-scaled)
    dim3 gqkv(QN / 128, MM / 128);
    mma_gemm<4><<<gqkv, 256, GSMEM>>>(xn, twqkv, bqkv, nullptr, nullptr, qkv, QN, DD);

    // 3. attention (tensor-core flash) -> fp16
    dim3 gf(SS / 128, HH, BB);
    flash_mma<<<gf, 256, FSMEM>>>(qkv, mask, at);

    // 4. O projection + residual -> h1 (fp32) in d_out
    dim3 g1(DD / 128, MM / 128);
    mma_gemm<2><<<g1, 256, GSMEM>>>(at, two, bo, x, out, nullptr, DD, DD);

    // 5. ln2 -> fp16
    ln_half_kernel<<<MM, 256>>>(out, ln2w, ln2b, xn);

    // 6. FFN up + relu  (N=4096) -> fp16
    dim3 g2(DFF / 128, MM / 128);
    mma_gemm<1><<<g2, 256, GSMEM>>>(xn, tw1, b1, nullptr, nullptr, ff, DFF, DD);

    // 7. FFN down + residual  (K=4096), fp32 out (in-place on d_out)
    mma_gemm<2><<<g1, 256, GSMEM>>>(ff, tw2, b2, out, out, nullptr, DD, DFF);
}